// round 7
// baseline (speedup 1.0000x reference)
#include <cuda_runtime.h>
#include <math.h>

#define NMAX 100000
#define EMAX 1600000
#define FIN  128
#define F1   64
#define F2   40
#define NB   ((NMAX + 1023) / 1024)   // 98 scan blocks

// ---------------- scratch (device globals) ---------------------------------
__device__ int   g_is64;                 // 1 if edge_index is int64, 0 if int32
__device__ int   g_cnt [NMAX];
__device__ int   g_off [NMAX + 1];
__device__ int   g_pos [NMAX];
__device__ int   g_bsum[NB];
__device__ int   g_boff[NB];
__device__ int   g_eidx[EMAX];           // src ids sorted by dst
__device__ float g_dinv[NMAX];
__device__ float g_xws [(size_t)NMAX * F1];  // (x@W1) * dinv[row]
__device__ float g_h   [(size_t)NMAX * F1];  // relu output
__device__ float g_hws [(size_t)NMAX * F2];  // (h@W2) * dinv[row]

// ---------------- dtype probe ----------------------------------------------
// int64 nonneg ids < 2^31  ->  all odd 32-bit words are 0.
// int32 ids               ->  odd words are real indices (mostly nonzero).
__global__ void k_probe(const int* __restrict__ ei32, int E) {
    if (threadIdx.x == 0 && blockIdx.x == 0) {
        int nz = 0;
        int lim = (E < 1024) ? E : 1024;
        for (int i = 0; i < lim; i++) nz |= ei32[2 * i + 1];
        g_is64 = (nz == 0) ? 1 : 0;
    }
}

__device__ __forceinline__ int load_src(const int* ei32, int E, int e) {
    return g_is64 ? ei32[2 * e] : ei32[e];
}
__device__ __forceinline__ int load_dst(const int* ei32, int E, int e) {
    return g_is64 ? ei32[2 * (E + e)] : ei32[E + e];
}

// ---------------- CSR build -------------------------------------------------
__global__ void k_zero(int n) {
    int i = blockIdx.x * blockDim.x + threadIdx.x;
    if (i < n) { g_cnt[i] = 0; g_pos[i] = 0; }
}

__global__ void k_hist(const int* __restrict__ ei32, int E, int n) {
    int e = blockIdx.x * blockDim.x + threadIdx.x;
    if (e >= E) return;
    int d = load_dst(ei32, E, e);
    if ((unsigned)d < (unsigned)n)           // hard clamp: never trap
        atomicAdd(&g_cnt[d], 1);
}

__global__ void k_scan1(int n) {
    __shared__ int sh[2][1024];
    int tid = threadIdx.x;
    int i = blockIdx.x * 1024 + tid;
    int x = (i < n) ? g_cnt[i] : 0;
    sh[0][tid] = x;
    int pin = 0;
    for (int off = 1; off < 1024; off <<= 1) {
        __syncthreads();
        int v = sh[pin][tid];
        if (tid >= off) v += sh[pin][tid - off];
        sh[1 - pin][tid] = v;
        pin = 1 - pin;
    }
    __syncthreads();
    int inc = sh[pin][tid];
    if (i < n) g_off[i] = inc - x;             // exclusive, pre-block-offset
    if (tid == 1023) g_bsum[blockIdx.x] = inc; // block total
}

__global__ void k_scan2(int n, int nb) {
    if (threadIdx.x == 0) {
        int run = 0;
        for (int b = 0; b < nb; b++) { g_boff[b] = run; run += g_bsum[b]; }
        g_off[n] = run;
    }
}

__global__ void k_scan3(int n) {
    int i = blockIdx.x * 1024 + threadIdx.x;
    if (i < n) g_off[i] += g_boff[blockIdx.x];
}

__global__ void k_dinvk(int n) {
    int i = blockIdx.x * blockDim.x + threadIdx.x;
    if (i < n) g_dinv[i] = rsqrtf((float)(g_cnt[i] + 1));  // +1 self-loop
}

__global__ void k_place(const int* __restrict__ ei32, int E, int n) {
    int e = blockIdx.x * blockDim.x + threadIdx.x;
    if (e >= E) return;
    int d = load_dst(ei32, E, e);
    int s = load_src(ei32, E, e);
    if ((unsigned)d >= (unsigned)n) return;  // clamp
    if ((unsigned)s >= (unsigned)n) s = 0;   // clamp (never trap)
    int slot = g_off[d] + atomicAdd(&g_pos[d], 1);
    if (slot < EMAX) g_eidx[slot] = s;
}

// ---------------- GEMM1: xws = (x @ W1) * dinv[row] ------------------------
// Block: 256 threads = 32 sub-rows x 8 col-groups; each thread: 2 rows x 8 cols.
__global__ void k_gemm1(const float* __restrict__ x,
                        const float* __restrict__ W, int n) {
    __shared__ float ws[FIN * F1];  // 32 KB
    int tid = threadIdx.x;
    for (int i = tid; i < FIN * F1; i += 256) ws[i] = W[i];
    __syncthreads();

    int sub = tid >> 3;            // 0..31
    int cg  = (tid & 7) * 8;       // column group start
    int r0 = blockIdx.x * 64 + sub;
    int r1 = r0 + 32;
    if (r0 >= n) return;
    bool v1 = (r1 < n);

    float a00 = 0.f, a01 = 0.f, a02 = 0.f, a03 = 0.f;
    float a04 = 0.f, a05 = 0.f, a06 = 0.f, a07 = 0.f;
    float a10 = 0.f, a11 = 0.f, a12 = 0.f, a13 = 0.f;
    float a14 = 0.f, a15 = 0.f, a16 = 0.f, a17 = 0.f;

    const float* xr0 = x + (size_t)r0 * FIN;
    const float* xr1 = x + (size_t)(v1 ? r1 : r0) * FIN;
#pragma unroll 4
    for (int k = 0; k < FIN; k++) {
        float xk0 = xr0[k];
        float xk1 = xr1[k];
        const float* wr = ws + k * F1 + cg;
        float w0 = wr[0], w1 = wr[1], w2 = wr[2], w3 = wr[3];
        float w4 = wr[4], w5 = wr[5], w6 = wr[6], w7 = wr[7];
        a00 = fmaf(xk0, w0, a00); a10 = fmaf(xk1, w0, a10);
        a01 = fmaf(xk0, w1, a01); a11 = fmaf(xk1, w1, a11);
        a02 = fmaf(xk0, w2, a02); a12 = fmaf(xk1, w2, a12);
        a03 = fmaf(xk0, w3, a03); a13 = fmaf(xk1, w3, a13);
        a04 = fmaf(xk0, w4, a04); a14 = fmaf(xk1, w4, a14);
        a05 = fmaf(xk0, w5, a05); a15 = fmaf(xk1, w5, a15);
        a06 = fmaf(xk0, w6, a06); a16 = fmaf(xk1, w6, a16);
        a07 = fmaf(xk0, w7, a07); a17 = fmaf(xk1, w7, a17);
    }

    float s0 = g_dinv[r0];
    float* o0 = g_xws + (size_t)r0 * F1 + cg;
    o0[0] = a00 * s0; o0[1] = a01 * s0; o0[2] = a02 * s0; o0[3] = a03 * s0;
    o0[4] = a04 * s0; o0[5] = a05 * s0; o0[6] = a06 * s0; o0[7] = a07 * s0;
    if (v1) {
        float s1 = g_dinv[r1];
        float* o1 = g_xws + (size_t)r1 * F1 + cg;
        o1[0] = a10 * s1; o1[1] = a11 * s1; o1[2] = a12 * s1; o1[3] = a13 * s1;
        o1[4] = a14 * s1; o1[5] = a15 * s1; o1[6] = a16 * s1; o1[7] = a17 * s1;
    }
}

// ---------------- aggregation layer1 (warp per node) + bias + relu ---------
__global__ void k_agg1(const float* __restrict__ b1, int n) {
    int lane = threadIdx.x & 31;
    int w = blockIdx.x * 8 + (threadIdx.x >> 5);
    if (w >= n) return;

    int beg = g_off[w], end = g_off[w + 1];
    size_t self = (size_t)w * F1;
    float a0 = g_xws[self + lane];          // self-loop contribution
    float a1 = g_xws[self + 32 + lane];
    for (int k = beg; k < end; k++) {
        int s = g_eidx[k];                  // lane-broadcast load
        size_t rb = (size_t)s * F1;
        a0 += g_xws[rb + lane];
        a1 += g_xws[rb + 32 + lane];
    }
    float sc = g_dinv[w];
    g_h[self + lane]      = fmaxf(fmaf(a0, sc, b1[lane]),      0.0f);
    g_h[self + 32 + lane] = fmaxf(fmaf(a1, sc, b1[32 + lane]), 0.0f);
}

// ---------------- GEMM2: hws = (h @ W2) * dinv[row] ------------------------
// Block: 256 threads = 64 sub-rows x 4 col-groups; each thread: 2 rows x 10 cols.
__global__ void k_gemm2(const float* __restrict__ W, int n) {
    __shared__ float ws[F1 * F2];  // 10.24 KB
    int tid = threadIdx.x;
    for (int i = tid; i < F1 * F2; i += 256) ws[i] = W[i];
    __syncthreads();

    int sub = tid >> 2;             // 0..63
    int cg  = (tid & 3) * 10;       // column group start
    int r0 = blockIdx.x * 128 + sub;
    int r1 = r0 + 64;
    if (r0 >= n) return;
    bool v1 = (r1 < n);

    float a00 = 0.f, a01 = 0.f, a02 = 0.f, a03 = 0.f, a04 = 0.f;
    float a05 = 0.f, a06 = 0.f, a07 = 0.f, a08 = 0.f, a09 = 0.f;
    float a10 = 0.f, a11 = 0.f, a12 = 0.f, a13 = 0.f, a14 = 0.f;
    float a15 = 0.f, a16 = 0.f, a17 = 0.f, a18 = 0.f, a19 = 0.f;

    const float* hr0 = g_h + (size_t)r0 * F1;
    const float* hr1 = g_h + (size_t)(v1 ? r1 : r0) * F1;
#pragma unroll 4
    for (int k = 0; k < F1; k++) {
        float h0 = hr0[k];
        float h1 = hr1[k];
        const float* wr = ws + k * F2 + cg;
        float w0 = wr[0], w1 = wr[1], w2 = wr[2], w3 = wr[3], w4 = wr[4];
        float w5 = wr[5], w6 = wr[6], w7 = wr[7], w8 = wr[8], w9 = wr[9];
        a00 = fmaf(h0, w0, a00); a10 = fmaf(h1, w0, a10);
        a01 = fmaf(h0, w1, a01); a11 = fmaf(h1, w1, a11);
        a02 = fmaf(h0, w2, a02); a12 = fmaf(h1, w2, a12);
        a03 = fmaf(h0, w3, a03); a13 = fmaf(h1, w3, a13);
        a04 = fmaf(h0, w4, a04); a14 = fmaf(h1, w4, a14);
        a05 = fmaf(h0, w5, a05); a15 = fmaf(h1, w5, a15);
        a06 = fmaf(h0, w6, a06); a16 = fmaf(h1, w6, a16);
        a07 = fmaf(h0, w7, a07); a17 = fmaf(h1, w7, a17);
        a08 = fmaf(h0, w8, a08); a18 = fmaf(h1, w8, a18);
        a09 = fmaf(h0, w9, a09); a19 = fmaf(h1, w9, a19);
    }

    float s0 = g_dinv[r0];
    float* o0 = g_hws + (size_t)r0 * F2 + cg;
    o0[0] = a00 * s0; o0[1] = a01 * s0; o0[2] = a02 * s0; o0[3] = a03 * s0;
    o0[4] = a04 * s0; o0[5] = a05 * s0; o0[6] = a06 * s0; o0[7] = a07 * s0;
    o0[8] = a08 * s0; o0[9] = a09 * s0;
    if (v1) {
        float s1 = g_dinv[r1];
        float* o1 = g_hws + (size_t)r1 * F2 + cg;
        o1[0] = a10 * s1; o1[1] = a11 * s1; o1[2] = a12 * s1; o1[3] = a13 * s1;
        o1[4] = a14 * s1; o1[5] = a15 * s1; o1[6] = a16 * s1; o1[7] = a17 * s1;
        o1[8] = a18 * s1; o1[9] = a19 * s1;
    }
}

// ---------------- aggregation layer2 + bias + log_softmax ------------------
__global__ void k_agg2(const float* __restrict__ b2, float* __restrict__ out, int n) {
    int lane = threadIdx.x & 31;
    int w = blockIdx.x * 8 + (threadIdx.x >> 5);
    if (w >= n) return;

    int beg = g_off[w], end = g_off[w + 1];
    size_t self = (size_t)w * F2;
    float a0 = g_hws[self + lane];
    float a1 = (lane < 8) ? g_hws[self + 32 + lane] : 0.0f;
    for (int k = beg; k < end; k++) {
        int s = g_eidx[k];
        size_t rb = (size_t)s * F2;
        a0 += g_hws[rb + lane];
        if (lane < 8) a1 += g_hws[rb + 32 + lane];
    }
    float sc = g_dinv[w];
    float z0 = fmaf(a0, sc, b2[lane]);
    float z1 = (lane < 8) ? fmaf(a1, sc, b2[32 + lane]) : -1e30f;

    float m = fmaxf(z0, z1);
#pragma unroll
    for (int o = 16; o > 0; o >>= 1)
        m = fmaxf(m, __shfl_xor_sync(0xFFFFFFFFu, m, o));

    float sum = expf(z0 - m) + ((lane < 8) ? expf(z1 - m) : 0.0f);
#pragma unroll
    for (int o = 16; o > 0; o >>= 1)
        sum += __shfl_xor_sync(0xFFFFFFFFu, sum, o);

    float lse = m + logf(sum);
    out[self + lane] = z0 - lse;
    if (lane < 8) out[self + 32 + lane] = z1 - lse;
}

// ---------------- launcher --------------------------------------------------
extern "C" void kernel_launch(void* const* d_in, const int* in_sizes, int n_in,
                              void* d_out, int out_size) {
    const float* x    = (const float*)d_in[0];
    const int*   ei32 = (const int*)d_in[1];   // int32 OR int64 words; probed
    const float* W1   = (const float*)d_in[2];
    const float* b1   = (const float*)d_in[3];
    const float* W2   = (const float*)d_in[4];
    const float* b2   = (const float*)d_in[5];
    float*       out  = (float*)d_out;

    int n = in_sizes[0] / FIN;       // 100000
    int E = in_sizes[1] / 2;         // 1600000 (element count is dtype-agnostic)

    const int B = 256;
    int gn = (n + B - 1) / B;
    int ge = (E + B - 1) / B;
    int nb = (n + 1023) / 1024;      // 98
    int ga = (n + 7) / 8;            // warp-per-node grids

    k_probe<<<1, 32>>>(ei32, E);
    k_zero <<<gn, B>>>(n);
    k_hist <<<ge, B>>>(ei32, E, n);
    k_scan1<<<nb, 1024>>>(n);
    k_scan2<<<1, 32>>>(n, nb);
    k_scan3<<<nb, 1024>>>(n);
    k_dinvk<<<gn, B>>>(n);
    k_place<<<ge, B>>>(ei32, E, n);

    k_gemm1<<<(n + 63) / 64, B>>>(x, W1, n);
    k_agg1 <<<ga, B>>>(b1, n);
    k_gemm2<<<(n + 127) / 128, B>>>(W2, n);
    k_agg2 <<<ga, B>>>(b2, out, n);
}

// round 8
// speedup vs baseline: 1.2346x; 1.2346x over previous
#include <cuda_runtime.h>
#include <math.h>

#define NMAX 100000
#define EMAX 1600000
#define FIN  128
#define F1   64
#define F2   40
#define NB   ((NMAX + 1023) / 1024)   // 98 scan blocks

// ---------------- scratch (device globals) ---------------------------------
__device__ int    g_is64;                // 1 if edge_index is int64, 0 if int32
__device__ int    g_cnt [NMAX];
__device__ int    g_off [NMAX + 1];
__device__ int    g_pos [NMAX];
__device__ int    g_bsum[NB];
__device__ int    g_boff[NB];
__device__ int    g_eidx[EMAX];          // src ids sorted by dst
__device__ float  g_dinv[NMAX];
__device__ float2 g_xws [(size_t)NMAX * F1 / 2];  // (x@W1)*dinv, float2 view
__device__ float2 g_h   [(size_t)NMAX * F1 / 2];  // relu output
__device__ float2 g_hws [(size_t)NMAX * F2 / 2];  // (h@W2)*dinv

// ---------------- dtype probe (parallel) ------------------------------------
// int64 nonneg ids < 2^31 -> all odd 32-bit words are 0; int32 -> mostly nonzero.
__global__ void k_probe(const int* __restrict__ ei32, int E) {
    int t = threadIdx.x;
    int nz = 0;
    int lim = (E < 1024) ? E : 1024;
    for (int i = t; i < lim; i += 256) nz |= ei32[2 * i + 1];
    int any = __syncthreads_or(nz);
    if (t == 0) g_is64 = (any == 0) ? 1 : 0;
}

__device__ __forceinline__ int load_src(const int* ei32, int E, int e) {
    return g_is64 ? ei32[2 * e] : ei32[e];
}
__device__ __forceinline__ int load_dst(const int* ei32, int E, int e) {
    return g_is64 ? ei32[2 * (E + e)] : ei32[E + e];
}

// ---------------- CSR build -------------------------------------------------
__global__ void k_zero(int n) {
    int i = blockIdx.x * blockDim.x + threadIdx.x;
    if (i < n) { g_cnt[i] = 0; g_pos[i] = 0; }
}

__global__ void k_hist(const int* __restrict__ ei32, int E, int n) {
    int e = blockIdx.x * blockDim.x + threadIdx.x;
    if (e >= E) return;
    int d = load_dst(ei32, E, e);
    if ((unsigned)d < (unsigned)n) atomicAdd(&g_cnt[d], 1);
}

__global__ void k_scan1(int n) {
    __shared__ int sh[2][1024];
    int tid = threadIdx.x;
    int i = blockIdx.x * 1024 + tid;
    int x = (i < n) ? g_cnt[i] : 0;
    sh[0][tid] = x;
    int pin = 0;
    for (int off = 1; off < 1024; off <<= 1) {
        __syncthreads();
        int v = sh[pin][tid];
        if (tid >= off) v += sh[pin][tid - off];
        sh[1 - pin][tid] = v;
        pin = 1 - pin;
    }
    __syncthreads();
    int inc = sh[pin][tid];
    if (i < n) g_off[i] = inc - x;             // exclusive, pre-block-offset
    if (tid == 1023) g_bsum[blockIdx.x] = inc; // block total
}

// parallel scan of the 98 block sums (single block of 128 threads)
__global__ void k_scan2(int n, int nb) {
    __shared__ int sh[2][128];
    int tid = threadIdx.x;
    int x = (tid < nb) ? g_bsum[tid] : 0;
    sh[0][tid] = x;
    int pin = 0;
    for (int off = 1; off < 128; off <<= 1) {
        __syncthreads();
        int v = sh[pin][tid];
        if (tid >= off) v += sh[pin][tid - off];
        sh[1 - pin][tid] = v;
        pin = 1 - pin;
    }
    __syncthreads();
    int inc = sh[pin][tid];
    if (tid < nb) g_boff[tid] = inc - x;       // exclusive
    if (tid == nb - 1) g_off[n] = inc;         // total == E
}

// add block offsets + compute dinv in the same pass
__global__ void k_scan3(int n) {
    int i = blockIdx.x * 1024 + threadIdx.x;
    if (i < n) {
        g_off[i] += g_boff[blockIdx.x];
        g_dinv[i] = rsqrtf((float)(g_cnt[i] + 1));   // +1 self-loop
    }
}

__global__ void k_place(const int* __restrict__ ei32, int E, int n) {
    int e = blockIdx.x * blockDim.x + threadIdx.x;
    if (e >= E) return;
    int d = load_dst(ei32, E, e);
    int s = load_src(ei32, E, e);
    if ((unsigned)d >= (unsigned)n) return;
    if ((unsigned)s >= (unsigned)n) s = 0;
    int slot = g_off[d] + atomicAdd(&g_pos[d], 1);
    if (slot < EMAX) g_eidx[slot] = s;
}

// ---------------- GEMM1: xws = (x @ W1) * dinv[row] ------------------------
// 256 thr = 32 sub-rows x 8 col-groups; thread: 2 rows x 8 cols, float4 loads.
__global__ void k_gemm1(const float* __restrict__ x,
                        const float* __restrict__ W, int n) {
    __shared__ float ws[FIN * F1];  // 32 KB
    int tid = threadIdx.x;
    for (int i = tid; i < FIN * F1 / 4; i += 256)
        ((float4*)ws)[i] = ((const float4*)W)[i];
    __syncthreads();

    int sub = tid >> 3;            // 0..31
    int cg  = (tid & 7) * 8;       // column group start (32B aligned)
    int r0 = blockIdx.x * 64 + sub;
    int r1 = r0 + 32;
    if (r0 >= n) return;
    bool v1 = (r1 < n);

    float a00 = 0.f, a01 = 0.f, a02 = 0.f, a03 = 0.f;
    float a04 = 0.f, a05 = 0.f, a06 = 0.f, a07 = 0.f;
    float a10 = 0.f, a11 = 0.f, a12 = 0.f, a13 = 0.f;
    float a14 = 0.f, a15 = 0.f, a16 = 0.f, a17 = 0.f;

    const float4* xr0 = (const float4*)(x + (size_t)r0 * FIN);
    const float4* xr1 = (const float4*)(x + (size_t)(v1 ? r1 : r0) * FIN);
#pragma unroll 8
    for (int k4 = 0; k4 < FIN / 4; k4++) {
        float4 xa = xr0[k4];
        float4 xb = xr1[k4];
        float x0[4] = {xa.x, xa.y, xa.z, xa.w};
        float x1[4] = {xb.x, xb.y, xb.z, xb.w};
#pragma unroll
        for (int kk = 0; kk < 4; kk++) {
            const float4* wr = (const float4*)(ws + (k4 * 4 + kk) * F1 + cg);
            float4 wa = wr[0];
            float4 wb = wr[1];
            float p0 = x0[kk], p1 = x1[kk];
            a00 = fmaf(p0, wa.x, a00); a10 = fmaf(p1, wa.x, a10);
            a01 = fmaf(p0, wa.y, a01); a11 = fmaf(p1, wa.y, a11);
            a02 = fmaf(p0, wa.z, a02); a12 = fmaf(p1, wa.z, a12);
            a03 = fmaf(p0, wa.w, a03); a13 = fmaf(p1, wa.w, a13);
            a04 = fmaf(p0, wb.x, a04); a14 = fmaf(p1, wb.x, a14);
            a05 = fmaf(p0, wb.y, a05); a15 = fmaf(p1, wb.y, a15);
            a06 = fmaf(p0, wb.z, a06); a16 = fmaf(p1, wb.z, a16);
            a07 = fmaf(p0, wb.w, a07); a17 = fmaf(p1, wb.w, a17);
        }
    }

    float s0 = g_dinv[r0];
    float4* o0 = (float4*)((float*)g_xws + (size_t)r0 * F1 + cg);
    o0[0] = make_float4(a00 * s0, a01 * s0, a02 * s0, a03 * s0);
    o0[1] = make_float4(a04 * s0, a05 * s0, a06 * s0, a07 * s0);
    if (v1) {
        float s1 = g_dinv[r1];
        float4* o1 = (float4*)((float*)g_xws + (size_t)r1 * F1 + cg);
        o1[0] = make_float4(a10 * s1, a11 * s1, a12 * s1, a13 * s1);
        o1[1] = make_float4(a14 * s1, a15 * s1, a16 * s1, a17 * s1);
    }
}

// ---------------- aggregation layer1 (warp per node) + bias + relu ---------
// Each lane owns float2 at feature 2*lane; one 256B gather per neighbor row.
__global__ void k_agg1(const float* __restrict__ b1, int n) {
    int lane = threadIdx.x & 31;
    int w = blockIdx.x * 8 + (threadIdx.x >> 5);
    if (w >= n) return;

    int beg = g_off[w], end = g_off[w + 1];
    size_t self = (size_t)w * (F1 / 2) + lane;
    float2 acc = g_xws[self];               // self-loop contribution
    int k = beg;
    for (; k + 1 < end; k += 2) {           // 2-edge unroll for MLP
        int s0 = g_eidx[k];
        int s1 = g_eidx[k + 1];
        float2 u = g_xws[(size_t)s0 * (F1 / 2) + lane];
        float2 v = g_xws[(size_t)s1 * (F1 / 2) + lane];
        acc.x += u.x + v.x;
        acc.y += u.y + v.y;
    }
    if (k < end) {
        int s0 = g_eidx[k];
        float2 u = g_xws[(size_t)s0 * (F1 / 2) + lane];
        acc.x += u.x;
        acc.y += u.y;
    }
    float sc = g_dinv[w];
    float bx = b1[2 * lane], by = b1[2 * lane + 1];
    float2 r;
    r.x = fmaxf(fmaf(acc.x, sc, bx), 0.0f);
    r.y = fmaxf(fmaf(acc.y, sc, by), 0.0f);
    g_h[self] = r;
}

// ---------------- GEMM2: hws = (h @ W2) * dinv[row] ------------------------
// 320 thr = 64 sub-rows x 5 col-groups; thread: 2 rows x 8 cols, float4 loads.
__global__ void k_gemm2(const float* __restrict__ W, int n) {
    __shared__ float ws[F1 * F2];  // 10.24 KB
    int tid = threadIdx.x;
    for (int i = tid; i < F1 * F2; i += 320) ws[i] = W[i];
    __syncthreads();

    int sub = tid / 5;              // 0..63
    int cg  = (tid % 5) * 8;        // column group start (32B aligned)
    int r0 = blockIdx.x * 128 + sub;
    int r1 = r0 + 64;
    if (r0 >= n) return;
    bool v1 = (r1 < n);

    float a00 = 0.f, a01 = 0.f, a02 = 0.f, a03 = 0.f;
    float a04 = 0.f, a05 = 0.f, a06 = 0.f, a07 = 0.f;
    float a10 = 0.f, a11 = 0.f, a12 = 0.f, a13 = 0.f;
    float a14 = 0.f, a15 = 0.f, a16 = 0.f, a17 = 0.f;

    const float4* hr0 = (const float4*)((const float*)g_h + (size_t)r0 * F1);
    const float4* hr1 = (const float4*)((const float*)g_h + (size_t)(v1 ? r1 : r0) * F1);
#pragma unroll 4
    for (int k4 = 0; k4 < F1 / 4; k4++) {
        float4 ha = hr0[k4];
        float4 hb = hr1[k4];
        float h0[4] = {ha.x, ha.y, ha.z, ha.w};
        float h1[4] = {hb.x, hb.y, hb.z, hb.w};
#pragma unroll
        for (int kk = 0; kk < 4; kk++) {
            const float4* wr = (const float4*)(ws + (k4 * 4 + kk) * F2 + cg);
            float4 wa = wr[0];
            float4 wb = wr[1];
            float p0 = h0[kk], p1 = h1[kk];
            a00 = fmaf(p0, wa.x, a00); a10 = fmaf(p1, wa.x, a10);
            a01 = fmaf(p0, wa.y, a01); a11 = fmaf(p1, wa.y, a11);
            a02 = fmaf(p0, wa.z, a02); a12 = fmaf(p1, wa.z, a12);
            a03 = fmaf(p0, wa.w, a03); a13 = fmaf(p1, wa.w, a13);
            a04 = fmaf(p0, wb.x, a04); a14 = fmaf(p1, wb.x, a14);
            a05 = fmaf(p0, wb.y, a05); a15 = fmaf(p1, wb.y, a15);
            a06 = fmaf(p0, wb.z, a06); a16 = fmaf(p1, wb.z, a16);
            a07 = fmaf(p0, wb.w, a07); a17 = fmaf(p1, wb.w, a17);
        }
    }

    float s0 = g_dinv[r0];
    float4* o0 = (float4*)((float*)g_hws + (size_t)r0 * F2 + cg);
    o0[0] = make_float4(a00 * s0, a01 * s0, a02 * s0, a03 * s0);
    o0[1] = make_float4(a04 * s0, a05 * s0, a06 * s0, a07 * s0);
    if (v1) {
        float s1 = g_dinv[r1];
        float4* o1 = (float4*)((float*)g_hws + (size_t)r1 * F2 + cg);
        o1[0] = make_float4(a10 * s1, a11 * s1, a12 * s1, a13 * s1);
        o1[1] = make_float4(a14 * s1, a15 * s1, a16 * s1, a17 * s1);
    }
}

// ---------------- aggregation layer2 + bias + log_softmax ------------------
// Lanes 0..19 own float2 at feature 2*lane (40 floats per node).
__global__ void k_agg2(const float* __restrict__ b2, float* __restrict__ out, int n) {
    int lane = threadIdx.x & 31;
    int w = blockIdx.x * 8 + (threadIdx.x >> 5);
    if (w >= n) return;

    bool act = (lane < F2 / 2);
    int li = act ? lane : 0;
    int beg = g_off[w], end = g_off[w + 1];
    size_t self = (size_t)w * (F2 / 2) + li;

    float2 acc = g_hws[self];
    int k = beg;
    for (; k + 1 < end; k += 2) {
        int s0 = g_eidx[k];
        int s1 = g_eidx[k + 1];
        float2 u = g_hws[(size_t)s0 * (F2 / 2) + li];
        float2 v = g_hws[(size_t)s1 * (F2 / 2) + li];
        acc.x += u.x + v.x;
        acc.y += u.y + v.y;
    }
    if (k < end) {
        float2 u = g_hws[(size_t)g_eidx[k] * (F2 / 2) + li];
        acc.x += u.x;
        acc.y += u.y;
    }

    float sc = g_dinv[w];
    float zx = fmaf(acc.x, sc, b2[2 * li]);
    float zy = fmaf(acc.y, sc, b2[2 * li + 1]);

    float m = act ? fmaxf(zx, zy) : -1e30f;
#pragma unroll
    for (int o = 16; o > 0; o >>= 1)
        m = fmaxf(m, __shfl_xor_sync(0xFFFFFFFFu, m, o));

    float sum = act ? (expf(zx - m) + expf(zy - m)) : 0.0f;
#pragma unroll
    for (int o = 16; o > 0; o >>= 1)
        sum += __shfl_xor_sync(0xFFFFFFFFu, sum, o);

    float lse = m + logf(sum);
    if (act) {
        float2* o2 = (float2*)(out + (size_t)w * F2 + 2 * li);
        *o2 = make_float2(zx - lse, zy - lse);
    }
}

// ---------------- launcher --------------------------------------------------
extern "C" void kernel_launch(void* const* d_in, const int* in_sizes, int n_in,
                              void* d_out, int out_size) {
    const float* x    = (const float*)d_in[0];
    const int*   ei32 = (const int*)d_in[1];   // int32 words (probed for int64)
    const float* W1   = (const float*)d_in[2];
    const float* b1   = (const float*)d_in[3];
    const float* W2   = (const float*)d_in[4];
    const float* b2   = (const float*)d_in[5];
    float*       out  = (float*)d_out;

    int n = in_sizes[0] / FIN;       // 100000
    int E = in_sizes[1] / 2;         // 1600000

    const int B = 256;
    int gn = (n + B - 1) / B;
    int ge = (E + B - 1) / B;
    int nb = (n + 1023) / 1024;      // 98
    int ga = (n + 7) / 8;            // warp-per-node grids

    k_probe<<<1, 256>>>(ei32, E);
    k_zero <<<gn, B>>>(n);
    k_hist <<<ge, B>>>(ei32, E, n);
    k_scan1<<<nb, 1024>>>(n);
    k_scan2<<<1, 128>>>(n, nb);
    k_scan3<<<nb, 1024>>>(n);
    k_place<<<ge, B>>>(ei32, E, n);

    k_gemm1<<<(n + 63) / 64, B>>>(x, W1, n);
    k_agg1 <<<ga, B>>>(b1, n);
    k_gemm2<<<(n + 127) / 128, 320>>>(W2, n);
    k_agg2 <<<ga, B>>>(b2, out, n);
}

// round 10
// speedup vs baseline: 1.4319x; 1.1599x over previous
#include <cuda_runtime.h>
#include <math.h>

#define NMAX 100000
#define EMAX 1600000
#define FIN  128
#define F1   64
#define F2   40
#define NB   ((NMAX + 1023) / 1024)   // 98 scan blocks

// ---------------- scratch (device globals) ---------------------------------
__device__ int    g_is64;                // 1 if edge_index is int64, 0 if int32
__device__ int    g_cnt [NMAX];
__device__ int    g_off [NMAX + 1];
__device__ int    g_pos [NMAX];
__device__ int    g_bsum[NB];
__device__ int    g_boff[NB];
__device__ int    g_eidx[EMAX];          // src ids sorted by dst
__device__ float  g_dinv[NMAX];
__device__ float2 g_xws [(size_t)NMAX * F1 / 2];  // (x@W1)*dinv, float2 view
__device__ float2 g_h   [(size_t)NMAX * F1 / 2];  // relu output
__device__ float2 g_hws [(size_t)NMAX * F2 / 2];  // (h@W2)*dinv

// ---------------- dtype probe (parallel) ------------------------------------
__global__ void k_probe(const int* __restrict__ ei32, int E) {
    int t = threadIdx.x;
    int nz = 0;
    int lim = (E < 1024) ? E : 1024;
    for (int i = t; i < lim; i += 256) nz |= ei32[2 * i + 1];
    int any = __syncthreads_or(nz);
    if (t == 0) g_is64 = (any == 0) ? 1 : 0;
}

// ---------------- CSR build -------------------------------------------------
__global__ void k_zero(int n) {
    int i = blockIdx.x * blockDim.x + threadIdx.x;
    if (i < n) { g_cnt[i] = 0; g_pos[i] = 0; }
}

__global__ void k_hist(const int* __restrict__ ei32, int E, int n) {
    int e = blockIdx.x * blockDim.x + threadIdx.x;
    if (e >= E) return;
    int d;
    if (g_is64) {
        const long long* dst64 = ((const long long*)ei32) + E;
        d = (int)dst64[e];                 // coalesced 8B
    } else {
        d = ei32[E + e];                   // coalesced 4B
    }
    if ((unsigned)d < (unsigned)n) atomicAdd(&g_cnt[d], 1);
}

__global__ void k_scan1(int n) {
    __shared__ int sh[2][1024];
    int tid = threadIdx.x;
    int i = blockIdx.x * 1024 + tid;
    int x = (i < n) ? g_cnt[i] : 0;
    sh[0][tid] = x;
    int pin = 0;
    for (int off = 1; off < 1024; off <<= 1) {
        __syncthreads();
        int v = sh[pin][tid];
        if (tid >= off) v += sh[pin][tid - off];
        sh[1 - pin][tid] = v;
        pin = 1 - pin;
    }
    __syncthreads();
    int inc = sh[pin][tid];
    if (i < n) g_off[i] = inc - x;             // exclusive, pre-block-offset
    if (tid == 1023) g_bsum[blockIdx.x] = inc; // block total
}

__global__ void k_scan2(int n, int nb) {
    __shared__ int sh[2][128];
    int tid = threadIdx.x;
    int x = (tid < nb) ? g_bsum[tid] : 0;
    sh[0][tid] = x;
    int pin = 0;
    for (int off = 1; off < 128; off <<= 1) {
        __syncthreads();
        int v = sh[pin][tid];
        if (tid >= off) v += sh[pin][tid - off];
        sh[1 - pin][tid] = v;
        pin = 1 - pin;
    }
    __syncthreads();
    int inc = sh[pin][tid];
    if (tid < nb) g_boff[tid] = inc - x;       // exclusive
    if (tid == nb - 1) g_off[n] = inc;         // total == E
}

__global__ void k_scan3(int n) {
    int i = blockIdx.x * 1024 + threadIdx.x;
    if (i < n) {
        g_off[i] += g_boff[blockIdx.x];
        g_dinv[i] = rsqrtf((float)(g_cnt[i] + 1));   // +1 self-loop
    }
}

__global__ void k_place(const int* __restrict__ ei32, int E, int n) {
    int e = blockIdx.x * blockDim.x + threadIdx.x;
    if (e >= E) return;
    int d, s;
    if (g_is64) {
        const long long* src64 = (const long long*)ei32;
        d = (int)src64[E + e];
        s = (int)src64[e];
    } else {
        d = ei32[E + e];
        s = ei32[e];
    }
    if ((unsigned)d >= (unsigned)n) return;
    if ((unsigned)s >= (unsigned)n) s = 0;
    int slot = g_off[d] + atomicAdd(&g_pos[d], 1);
    if (slot < EMAX) g_eidx[slot] = s;
}

// ---------------- GEMM1: xws = (x @ W1) * dinv[row] ------------------------
// 256 thr = 32 sub-rows x 8 col-groups; thread: 4 rows x 8 cols, float4 loads.
__global__ void __launch_bounds__(256) k_gemm1(const float* __restrict__ x,
                                               const float* __restrict__ W, int n) {
    __shared__ float ws[FIN * F1];  // 32 KB
    int tid = threadIdx.x;
    for (int i = tid; i < FIN * F1 / 4; i += 256)
        ((float4*)ws)[i] = ((const float4*)W)[i];
    __syncthreads();

    int sub = tid >> 3;            // 0..31
    int cg  = (tid & 7) * 8;       // column group start (32B aligned)
    int base = blockIdx.x * 128 + sub;

    float a[4][8];
#pragma unroll
    for (int r = 0; r < 4; r++)
#pragma unroll
        for (int j = 0; j < 8; j++) a[r][j] = 0.0f;

    int rr[4];
    const float4* xr[4];
#pragma unroll
    for (int r = 0; r < 4; r++) {
        int row = base + r * 32;
        rr[r] = (row < n) ? row : (n - 1);        // clamp; dup work, no trap
        xr[r] = (const float4*)(x + (size_t)rr[r] * FIN);
    }

#pragma unroll 4
    for (int k4 = 0; k4 < FIN / 4; k4++) {
        float4 xv[4];
#pragma unroll
        for (int r = 0; r < 4; r++) xv[r] = xr[r][k4];
#pragma unroll
        for (int kk = 0; kk < 4; kk++) {
            const float4* wr = (const float4*)(ws + (k4 * 4 + kk) * F1 + cg);
            float4 wa = wr[0];
            float4 wb = wr[1];
#pragma unroll
            for (int r = 0; r < 4; r++) {
                float p = (kk == 0) ? xv[r].x : (kk == 1) ? xv[r].y
                        : (kk == 2) ? xv[r].z : xv[r].w;
                a[r][0] = fmaf(p, wa.x, a[r][0]);
                a[r][1] = fmaf(p, wa.y, a[r][1]);
                a[r][2] = fmaf(p, wa.z, a[r][2]);
                a[r][3] = fmaf(p, wa.w, a[r][3]);
                a[r][4] = fmaf(p, wb.x, a[r][4]);
                a[r][5] = fmaf(p, wb.y, a[r][5]);
                a[r][6] = fmaf(p, wb.z, a[r][6]);
                a[r][7] = fmaf(p, wb.w, a[r][7]);
            }
        }
    }

#pragma unroll
    for (int r = 0; r < 4; r++) {
        int row = base + r * 32;
        if (row >= n) break;
        float s = g_dinv[row];
        float4* o = (float4*)((float*)g_xws + (size_t)row * F1 + cg);
        o[0] = make_float4(a[r][0] * s, a[r][1] * s, a[r][2] * s, a[r][3] * s);
        o[1] = make_float4(a[r][4] * s, a[r][5] * s, a[r][6] * s, a[r][7] * s);
    }
}

// ---------------- aggregation layer1 (warp per node, 4-edge MLP) -----------
__global__ void k_agg1(const float* __restrict__ b1, int n) {
    int lane = threadIdx.x & 31;
    int w = blockIdx.x * 8 + (threadIdx.x >> 5);
    if (w >= n) return;

    int beg = g_off[w], end = g_off[w + 1];
    size_t self = (size_t)w * (F1 / 2) + lane;
    float2 acc = g_xws[self];               // self-loop contribution
    int k = beg;
    for (; k + 3 < end; k += 4) {           // 4 independent gathers in flight
        int s0 = g_eidx[k];
        int s1 = g_eidx[k + 1];
        int s2 = g_eidx[k + 2];
        int s3 = g_eidx[k + 3];
        float2 u0 = g_xws[(size_t)s0 * (F1 / 2) + lane];
        float2 u1 = g_xws[(size_t)s1 * (F1 / 2) + lane];
        float2 u2 = g_xws[(size_t)s2 * (F1 / 2) + lane];
        float2 u3 = g_xws[(size_t)s3 * (F1 / 2) + lane];
        acc.x += (u0.x + u1.x) + (u2.x + u3.x);
        acc.y += (u0.y + u1.y) + (u2.y + u3.y);
    }
    for (; k < end; k++) {
        float2 u = g_xws[(size_t)g_eidx[k] * (F1 / 2) + lane];
        acc.x += u.x;
        acc.y += u.y;
    }
    float sc = g_dinv[w];
    float bx = b1[2 * lane], by = b1[2 * lane + 1];
    float2 r;
    r.x = fmaxf(fmaf(acc.x, sc, bx), 0.0f);
    r.y = fmaxf(fmaf(acc.y, sc, by), 0.0f);
    g_h[self] = r;
}

// ---------------- GEMM2: hws = (h @ W2) * dinv[row] ------------------------
// 320 thr = 64 sub-rows x 5 col-groups; thread: 2 rows x 8 cols, float4 loads.
__global__ void k_gemm2(const float* __restrict__ W, int n) {
    __shared__ float ws[F1 * F2];  // 10.24 KB
    int tid = threadIdx.x;
    for (int i = tid; i < F1 * F2; i += 320) ws[i] = W[i];
    __syncthreads();

    int sub = tid / 5;              // 0..63
    int cg  = (tid % 5) * 8;        // column group start (32B aligned)
    int r0 = blockIdx.x * 128 + sub;
    int r1 = r0 + 64;
    if (r0 >= n) return;
    bool v1 = (r1 < n);

    float a00 = 0.f, a01 = 0.f, a02 = 0.f, a03 = 0.f;
    float a04 = 0.f, a05 = 0.f, a06 = 0.f, a07 = 0.f;
    float a10 = 0.f, a11 = 0.f, a12 = 0.f, a13 = 0.f;
    float a14 = 0.f, a15 = 0.f, a16 = 0.f, a17 = 0.f;

    const float4* hr0 = (const float4*)((const float*)g_h + (size_t)r0 * F1);
    const float4* hr1 = (const float4*)((const float*)g_h + (size_t)(v1 ? r1 : r0) * F1);
#pragma unroll 4
    for (int k4 = 0; k4 < F1 / 4; k4++) {
        float4 ha = hr0[k4];
        float4 hb = hr1[k4];
        float h0[4] = {ha.x, ha.y, ha.z, ha.w};
        float h1[4] = {hb.x, hb.y, hb.z, hb.w};
#pragma unroll
        for (int kk = 0; kk < 4; kk++) {
            const float4* wr = (const float4*)(ws + (k4 * 4 + kk) * F2 + cg);
            float4 wa = wr[0];
            float4 wb = wr[1];
            float p0 = h0[kk], p1 = h1[kk];
            a00 = fmaf(p0, wa.x, a00); a10 = fmaf(p1, wa.x, a10);
            a01 = fmaf(p0, wa.y, a01); a11 = fmaf(p1, wa.y, a11);
            a02 = fmaf(p0, wa.z, a02); a12 = fmaf(p1, wa.z, a12);
            a03 = fmaf(p0, wa.w, a03); a13 = fmaf(p1, wa.w, a13);
            a04 = fmaf(p0, wb.x, a04); a14 = fmaf(p1, wb.x, a14);
            a05 = fmaf(p0, wb.y, a05); a15 = fmaf(p1, wb.y, a15);
            a06 = fmaf(p0, wb.z, a06); a16 = fmaf(p1, wb.z, a16);
            a07 = fmaf(p0, wb.w, a07); a17 = fmaf(p1, wb.w, a17);
        }
    }

    float s0 = g_dinv[r0];
    float4* o0 = (float4*)((float*)g_hws + (size_t)r0 * F2 + cg);
    o0[0] = make_float4(a00 * s0, a01 * s0, a02 * s0, a03 * s0);
    o0[1] = make_float4(a04 * s0, a05 * s0, a06 * s0, a07 * s0);
    if (v1) {
        float s1 = g_dinv[r1];
        float4* o1 = (float4*)((float*)g_hws + (size_t)r1 * F2 + cg);
        o1[0] = make_float4(a10 * s1, a11 * s1, a12 * s1, a13 * s1);
        o1[1] = make_float4(a14 * s1, a15 * s1, a16 * s1, a17 * s1);
    }
}

// ---------------- aggregation layer2 + bias + log_softmax (4-edge MLP) -----
__global__ void k_agg2(const float* __restrict__ b2, float* __restrict__ out, int n) {
    int lane = threadIdx.x & 31;
    int w = blockIdx.x * 8 + (threadIdx.x >> 5);
    if (w >= n) return;

    bool act = (lane < F2 / 2);
    int li = act ? lane : 0;
    int beg = g_off[w], end = g_off[w + 1];
    size_t self = (size_t)w * (F2 / 2) + li;

    float2 acc = g_hws[self];
    int k = beg;
    for (; k + 3 < end; k += 4) {
        int s0 = g_eidx[k];
        int s1 = g_eidx[k + 1];
        int s2 = g_eidx[k + 2];
        int s3 = g_eidx[k + 3];
        float2 u0 = g_hws[(size_t)s0 * (F2 / 2) + li];
        float2 u1 = g_hws[(size_t)s1 * (F2 / 2) + li];
        float2 u2 = g_hws[(size_t)s2 * (F2 / 2) + li];
        float2 u3 = g_hws[(size_t)s3 * (F2 / 2) + li];
        acc.x += (u0.x + u1.x) + (u2.x + u3.x);
        acc.y += (u0.y + u1.y) + (u2.y + u3.y);
    }
    for (; k < end; k++) {
        float2 u = g_hws[(size_t)g_eidx[k] * (F2 / 2) + li];
        acc.x += u.x;
        acc.y += u.y;
    }

    float sc = g_dinv[w];
    float zx = fmaf(acc.x, sc, b2[2 * li]);
    float zy = fmaf(acc.y, sc, b2[2 * li + 1]);

    float m = act ? fmaxf(zx, zy) : -1e30f;
#pragma unroll
    for (int o = 16; o > 0; o >>= 1)
        m = fmaxf(m, __shfl_xor_sync(0xFFFFFFFFu, m, o));

    float sum = act ? (expf(zx - m) + expf(zy - m)) : 0.0f;
#pragma unroll
    for (int o = 16; o > 0; o >>= 1)
        sum += __shfl_xor_sync(0xFFFFFFFFu, sum, o);

    float lse = m + logf(sum);
    if (act) {
        float2* o2 = (float2*)(out + (size_t)w * F2 + 2 * li);
        *o2 = make_float2(zx - lse, zy - lse);
    }
}

// ---------------- launcher --------------------------------------------------
extern "C" void kernel_launch(void* const* d_in, const int* in_sizes, int n_in,
                              void* d_out, int out_size) {
    const float* x    = (const float*)d_in[0];
    const int*   ei32 = (const int*)d_in[1];   // int32 words (probed for int64)
    const float* W1   = (const float*)d_in[2];
    const float* b1   = (const float*)d_in[3];
    const float* W2   = (const float*)d_in[4];
    const float* b2   = (const float*)d_in[5];
    float*       out  = (float*)d_out;

    int n = in_sizes[0] / FIN;       // 100000
    int E = in_sizes[1] / 2;         // 1600000

    const int B = 256;
    int gn = (n + B - 1) / B;
    int ge = (E + B - 1) / B;
    int nb = (n + 1023) / 1024;      // 98
    int ga = (n + 7) / 8;            // warp-per-node grids

    k_probe<<<1, 256>>>(ei32, E);
    k_zero <<<gn, B>>>(n);
    k_hist <<<ge, B>>>(ei32, E, n);
    k_scan1<<<nb, 1024>>>(n);
    k_scan2<<<1, 128>>>(n, nb);
    k_scan3<<<nb, 1024>>>(n);
    k_place<<<ge, B>>>(ei32, E, n);

    k_gemm1<<<(n + 127) / 128, B>>>(x, W1, n);
    k_agg1 <<<ga, B>>>(b1, n);
    k_gemm2<<<(n + 127) / 128, 320>>>(W2, n);
    k_agg2 <<<ga, B>>>(b2, out, n);
}

// round 11
// speedup vs baseline: 1.4526x; 1.0145x over previous
#include <cuda_runtime.h>
#include <math.h>

#define NMAX 100000
#define EMAX 1600000
#define FIN  128
#define F1   64
#define F2   40
#define NB   ((NMAX + 1023) / 1024)   // 98 scan blocks

// ---------------- scratch (device globals) ---------------------------------
__device__ int    g_is64;                // 1 if edge_index is int64, 0 if int32
__device__ int    g_cnt [NMAX];
__device__ int    g_off [NMAX + 1];
__device__ int    g_pos [NMAX];
__device__ int    g_bsum[NB];
__device__ int    g_boff[NB];
__device__ int    g_eidx[EMAX];          // src ids sorted by dst
__device__ float  g_dinv[NMAX];
__device__ float2 g_xw  [(size_t)NMAX * F1 / 2];  // RAW x@W1 (unscaled)
__device__ float2 g_h   [(size_t)NMAX * F1 / 2];  // relu output
__device__ float2 g_hws [(size_t)NMAX * F2 / 2];  // (h@W2)*dinv

// ---------------- fused: zero counters + dtype probe ------------------------
__global__ void k_zero_probe(const int* __restrict__ ei32, int E, int n) {
    if (blockIdx.x == 0) {
        int t = threadIdx.x;
        int nz = 0;
        int lim = (E < 1024) ? E : 1024;
        for (int i = t; i < lim; i += 256) nz |= ei32[2 * i + 1];
        int any = __syncthreads_or(nz);
        if (t == 0) g_is64 = (any == 0) ? 1 : 0;
    } else {
        int i = (blockIdx.x - 1) * 256 + threadIdx.x;
        if (i < n) { g_cnt[i] = 0; g_pos[i] = 0; }
    }
}

// ---------------- fused: GEMM1 (raw) + degree histogram ---------------------
// First gemmBlocks blocks: 32 sub-rows x 8 col-groups, thread = 4 rows x 8 cols.
// Remaining blocks: histogram over dst.
__global__ void __launch_bounds__(256)
k_gemm1_hist(const float* __restrict__ x, const float* __restrict__ W,
             const int* __restrict__ ei32, int E, int n, int gemmBlocks) {
    __shared__ float ws[FIN * F1];  // 32 KB (idle for hist role)
    int tid = threadIdx.x;

    if (blockIdx.x >= gemmBlocks) {
        // ---- histogram role ----
        int e = (blockIdx.x - gemmBlocks) * 256 + tid;
        if (e >= E) return;
        int d;
        if (g_is64) d = (int)(((const long long*)ei32) + E)[e];
        else        d = ei32[E + e];
        if ((unsigned)d < (unsigned)n) atomicAdd(&g_cnt[d], 1);
        return;
    }

    // ---- GEMM1 role (raw output, no dinv) ----
    for (int i = tid; i < FIN * F1 / 4; i += 256)
        ((float4*)ws)[i] = ((const float4*)W)[i];
    __syncthreads();

    int sub = tid >> 3;            // 0..31
    int cg  = (tid & 7) * 8;       // column group start (32B aligned)
    int base = blockIdx.x * 128 + sub;

    float a[4][8];
#pragma unroll
    for (int r = 0; r < 4; r++)
#pragma unroll
        for (int j = 0; j < 8; j++) a[r][j] = 0.0f;

    const float4* xr[4];
#pragma unroll
    for (int r = 0; r < 4; r++) {
        int row = base + r * 32;
        int rc = (row < n) ? row : (n - 1);       // clamp; dup work, no trap
        xr[r] = (const float4*)(x + (size_t)rc * FIN);
    }

#pragma unroll 4
    for (int k4 = 0; k4 < FIN / 4; k4++) {
        float4 xv[4];
#pragma unroll
        for (int r = 0; r < 4; r++) xv[r] = xr[r][k4];
#pragma unroll
        for (int kk = 0; kk < 4; kk++) {
            const float4* wr = (const float4*)(ws + (k4 * 4 + kk) * F1 + cg);
            float4 wa = wr[0];
            float4 wb = wr[1];
#pragma unroll
            for (int r = 0; r < 4; r++) {
                float p = (kk == 0) ? xv[r].x : (kk == 1) ? xv[r].y
                        : (kk == 2) ? xv[r].z : xv[r].w;
                a[r][0] = fmaf(p, wa.x, a[r][0]);
                a[r][1] = fmaf(p, wa.y, a[r][1]);
                a[r][2] = fmaf(p, wa.z, a[r][2]);
                a[r][3] = fmaf(p, wa.w, a[r][3]);
                a[r][4] = fmaf(p, wb.x, a[r][4]);
                a[r][5] = fmaf(p, wb.y, a[r][5]);
                a[r][6] = fmaf(p, wb.z, a[r][6]);
                a[r][7] = fmaf(p, wb.w, a[r][7]);
            }
        }
    }

#pragma unroll
    for (int r = 0; r < 4; r++) {
        int row = base + r * 32;
        if (row >= n) break;
        float4* o = (float4*)((float*)g_xw + (size_t)row * F1 + cg);
        o[0] = make_float4(a[r][0], a[r][1], a[r][2], a[r][3]);
        o[1] = make_float4(a[r][4], a[r][5], a[r][6], a[r][7]);
    }
}

// ---------------- scans ------------------------------------------------------
__global__ void k_scan1(int n) {
    __shared__ int sh[2][1024];
    int tid = threadIdx.x;
    int i = blockIdx.x * 1024 + tid;
    int x = (i < n) ? g_cnt[i] : 0;
    sh[0][tid] = x;
    int pin = 0;
    for (int off = 1; off < 1024; off <<= 1) {
        __syncthreads();
        int v = sh[pin][tid];
        if (tid >= off) v += sh[pin][tid - off];
        sh[1 - pin][tid] = v;
        pin = 1 - pin;
    }
    __syncthreads();
    int inc = sh[pin][tid];
    if (i < n) g_off[i] = inc - x;             // exclusive, pre-block-offset
    if (tid == 1023) g_bsum[blockIdx.x] = inc; // block total
}

__global__ void k_scan2(int n, int nb) {
    __shared__ int sh[2][128];
    int tid = threadIdx.x;
    int x = (tid < nb) ? g_bsum[tid] : 0;
    sh[0][tid] = x;
    int pin = 0;
    for (int off = 1; off < 128; off <<= 1) {
        __syncthreads();
        int v = sh[pin][tid];
        if (tid >= off) v += sh[pin][tid - off];
        sh[1 - pin][tid] = v;
        pin = 1 - pin;
    }
    __syncthreads();
    int inc = sh[pin][tid];
    if (tid < nb) g_boff[tid] = inc - x;       // exclusive
    if (tid == nb - 1) g_off[n] = inc;         // total == E
}

__global__ void k_scan3(int n) {
    int i = blockIdx.x * 1024 + threadIdx.x;
    if (i < n) {
        g_off[i] += g_boff[blockIdx.x];
        g_dinv[i] = rsqrtf((float)(g_cnt[i] + 1));   // +1 self-loop
    }
}

__global__ void k_place(const int* __restrict__ ei32, int E, int n) {
    int e = blockIdx.x * blockDim.x + threadIdx.x;
    if (e >= E) return;
    int d, s;
    if (g_is64) {
        const long long* e64 = (const long long*)ei32;
        d = (int)e64[E + e];
        s = (int)e64[e];
    } else {
        d = ei32[E + e];
        s = ei32[e];
    }
    if ((unsigned)d >= (unsigned)n) return;
    if ((unsigned)s >= (unsigned)n) s = 0;
    int slot = g_off[d] + atomicAdd(&g_pos[d], 1);
    if (slot < EMAX) g_eidx[slot] = s;
}

// ---------------- aggregation layer1 (warp/node, 8-edge MLP, dinv[s]) ------
__global__ void k_agg1(const float* __restrict__ b1, int n) {
    int lane = threadIdx.x & 31;
    int w = blockIdx.x * 8 + (threadIdx.x >> 5);
    if (w >= n) return;

    int beg = g_off[w], end = g_off[w + 1];
    float sc = g_dinv[w];
    size_t self = (size_t)w * (F1 / 2) + lane;
    float2 sv = g_xw[self];
    float2 acc = make_float2(sv.x * sc, sv.y * sc);   // self: dinv[w]*xw[w]

    int k = beg;
    for (; k + 7 < end; k += 8) {           // 8 independent gathers in flight
        int s0 = g_eidx[k],     s1 = g_eidx[k + 1];
        int s2 = g_eidx[k + 2], s3 = g_eidx[k + 3];
        int s4 = g_eidx[k + 4], s5 = g_eidx[k + 5];
        int s6 = g_eidx[k + 6], s7 = g_eidx[k + 7];
        float d0 = g_dinv[s0], d1 = g_dinv[s1], d2 = g_dinv[s2], d3 = g_dinv[s3];
        float d4 = g_dinv[s4], d5 = g_dinv[s5], d6 = g_dinv[s6], d7 = g_dinv[s7];
        float2 u0 = g_xw[(size_t)s0 * (F1 / 2) + lane];
        float2 u1 = g_xw[(size_t)s1 * (F1 / 2) + lane];
        float2 u2 = g_xw[(size_t)s2 * (F1 / 2) + lane];
        float2 u3 = g_xw[(size_t)s3 * (F1 / 2) + lane];
        float2 u4 = g_xw[(size_t)s4 * (F1 / 2) + lane];
        float2 u5 = g_xw[(size_t)s5 * (F1 / 2) + lane];
        float2 u6 = g_xw[(size_t)s6 * (F1 / 2) + lane];
        float2 u7 = g_xw[(size_t)s7 * (F1 / 2) + lane];
        acc.x = fmaf(d0, u0.x, acc.x); acc.y = fmaf(d0, u0.y, acc.y);
        acc.x = fmaf(d1, u1.x, acc.x); acc.y = fmaf(d1, u1.y, acc.y);
        acc.x = fmaf(d2, u2.x, acc.x); acc.y = fmaf(d2, u2.y, acc.y);
        acc.x = fmaf(d3, u3.x, acc.x); acc.y = fmaf(d3, u3.y, acc.y);
        acc.x = fmaf(d4, u4.x, acc.x); acc.y = fmaf(d4, u4.y, acc.y);
        acc.x = fmaf(d5, u5.x, acc.x); acc.y = fmaf(d5, u5.y, acc.y);
        acc.x = fmaf(d6, u6.x, acc.x); acc.y = fmaf(d6, u6.y, acc.y);
        acc.x = fmaf(d7, u7.x, acc.x); acc.y = fmaf(d7, u7.y, acc.y);
    }
    for (; k < end; k++) {
        int s = g_eidx[k];
        float ds = g_dinv[s];
        float2 u = g_xw[(size_t)s * (F1 / 2) + lane];
        acc.x = fmaf(ds, u.x, acc.x);
        acc.y = fmaf(ds, u.y, acc.y);
    }

    float bx = b1[2 * lane], by = b1[2 * lane + 1];
    float2 r;
    r.x = fmaxf(fmaf(acc.x, sc, bx), 0.0f);
    r.y = fmaxf(fmaf(acc.y, sc, by), 0.0f);
    g_h[self] = r;
}

// ---------------- GEMM2: hws = (h @ W2) * dinv[row] ------------------------
__global__ void k_gemm2(const float* __restrict__ W, int n) {
    __shared__ float ws[F1 * F2];  // 10.24 KB
    int tid = threadIdx.x;
    for (int i = tid; i < F1 * F2; i += 320) ws[i] = W[i];
    __syncthreads();

    int sub = tid / 5;              // 0..63
    int cg  = (tid % 5) * 8;        // column group start (32B aligned)
    int r0 = blockIdx.x * 128 + sub;
    int r1 = r0 + 64;
    if (r0 >= n) return;
    bool v1 = (r1 < n);

    float a00 = 0.f, a01 = 0.f, a02 = 0.f, a03 = 0.f;
    float a04 = 0.f, a05 = 0.f, a06 = 0.f, a07 = 0.f;
    float a10 = 0.f, a11 = 0.f, a12 = 0.f, a13 = 0.f;
    float a14 = 0.f, a15 = 0.f, a16 = 0.f, a17 = 0.f;

    const float4* hr0 = (const float4*)((const float*)g_h + (size_t)r0 * F1);
    const float4* hr1 = (const float4*)((const float*)g_h + (size_t)(v1 ? r1 : r0) * F1);
#pragma unroll 4
    for (int k4 = 0; k4 < F1 / 4; k4++) {
        float4 ha = hr0[k4];
        float4 hb = hr1[k4];
        float h0[4] = {ha.x, ha.y, ha.z, ha.w};
        float h1[4] = {hb.x, hb.y, hb.z, hb.w};
#pragma unroll
        for (int kk = 0; kk < 4; kk++) {
            const float4* wr = (const float4*)(ws + (k4 * 4 + kk) * F2 + cg);
            float4 wa = wr[0];
            float4 wb = wr[1];
            float p0 = h0[kk], p1 = h1[kk];
            a00 = fmaf(p0, wa.x, a00); a10 = fmaf(p1, wa.x, a10);
            a01 = fmaf(p0, wa.y, a01); a11 = fmaf(p1, wa.y, a11);
            a02 = fmaf(p0, wa.z, a02); a12 = fmaf(p1, wa.z, a12);
            a03 = fmaf(p0, wa.w, a03); a13 = fmaf(p1, wa.w, a13);
            a04 = fmaf(p0, wb.x, a04); a14 = fmaf(p1, wb.x, a14);
            a05 = fmaf(p0, wb.y, a05); a15 = fmaf(p1, wb.y, a15);
            a06 = fmaf(p0, wb.z, a06); a16 = fmaf(p1, wb.z, a16);
            a07 = fmaf(p0, wb.w, a07); a17 = fmaf(p1, wb.w, a17);
        }
    }

    float s0 = g_dinv[r0];
    float4* o0 = (float4*)((float*)g_hws + (size_t)r0 * F2 + cg);
    o0[0] = make_float4(a00 * s0, a01 * s0, a02 * s0, a03 * s0);
    o0[1] = make_float4(a04 * s0, a05 * s0, a06 * s0, a07 * s0);
    if (v1) {
        float s1 = g_dinv[r1];
        float4* o1 = (float4*)((float*)g_hws + (size_t)r1 * F2 + cg);
        o1[0] = make_float4(a10 * s1, a11 * s1, a12 * s1, a13 * s1);
        o1[1] = make_float4(a14 * s1, a15 * s1, a16 * s1, a17 * s1);
    }
}

// ---------------- aggregation layer2 + bias + log_softmax (8-edge MLP) -----
__global__ void k_agg2(const float* __restrict__ b2, float* __restrict__ out, int n) {
    int lane = threadIdx.x & 31;
    int w = blockIdx.x * 8 + (threadIdx.x >> 5);
    if (w >= n) return;

    bool act = (lane < F2 / 2);
    int li = act ? lane : 0;
    int beg = g_off[w], end = g_off[w + 1];
    size_t self = (size_t)w * (F2 / 2) + li;

    float2 acc = g_hws[self];
    int k = beg;
    for (; k + 7 < end; k += 8) {
        int s0 = g_eidx[k],     s1 = g_eidx[k + 1];
        int s2 = g_eidx[k + 2], s3 = g_eidx[k + 3];
        int s4 = g_eidx[k + 4], s5 = g_eidx[k + 5];
        int s6 = g_eidx[k + 6], s7 = g_eidx[k + 7];
        float2 u0 = g_hws[(size_t)s0 * (F2 / 2) + li];
        float2 u1 = g_hws[(size_t)s1 * (F2 / 2) + li];
        float2 u2 = g_hws[(size_t)s2 * (F2 / 2) + li];
        float2 u3 = g_hws[(size_t)s3 * (F2 / 2) + li];
        float2 u4 = g_hws[(size_t)s4 * (F2 / 2) + li];
        float2 u5 = g_hws[(size_t)s5 * (F2 / 2) + li];
        float2 u6 = g_hws[(size_t)s6 * (F2 / 2) + li];
        float2 u7 = g_hws[(size_t)s7 * (F2 / 2) + li];
        acc.x += ((u0.x + u1.x) + (u2.x + u3.x)) + ((u4.x + u5.x) + (u6.x + u7.x));
        acc.y += ((u0.y + u1.y) + (u2.y + u3.y)) + ((u4.y + u5.y) + (u6.y + u7.y));
    }
    for (; k < end; k++) {
        float2 u = g_hws[(size_t)g_eidx[k] * (F2 / 2) + li];
        acc.x += u.x;
        acc.y += u.y;
    }

    float sc = g_dinv[w];
    float zx = fmaf(acc.x, sc, b2[2 * li]);
    float zy = fmaf(acc.y, sc, b2[2 * li + 1]);

    float m = act ? fmaxf(zx, zy) : -1e30f;
#pragma unroll
    for (int o = 16; o > 0; o >>= 1)
        m = fmaxf(m, __shfl_xor_sync(0xFFFFFFFFu, m, o));

    float sum = act ? (expf(zx - m) + expf(zy - m)) : 0.0f;
#pragma unroll
    for (int o = 16; o > 0; o >>= 1)
        sum += __shfl_xor_sync(0xFFFFFFFFu, sum, o);

    float lse = m + logf(sum);
    if (act) {
        float2* o2 = (float2*)(out + (size_t)w * F2 + 2 * li);
        *o2 = make_float2(zx - lse, zy - lse);
    }
}

// ---------------- launcher --------------------------------------------------
extern "C" void kernel_launch(void* const* d_in, const int* in_sizes, int n_in,
                              void* d_out, int out_size) {
    const float* x    = (const float*)d_in[0];
    const int*   ei32 = (const int*)d_in[1];   // int32 words (probed for int64)
    const float* W1   = (const float*)d_in[2];
    const float* b1   = (const float*)d_in[3];
    const float* W2   = (const float*)d_in[4];
    const float* b2   = (const float*)d_in[5];
    float*       out  = (float*)d_out;

    int n = in_sizes[0] / FIN;       // 100000
    int E = in_sizes[1] / 2;         // 1600000

    const int B = 256;
    int gn = (n + B - 1) / B;
    int ge = (E + B - 1) / B;
    int nb = (n + 1023) / 1024;      // 98
    int ga = (n + 7) / 8;            // warp-per-node grids
    int gemmBlocks = (n + 127) / 128;

    k_zero_probe<<<gn + 1, B>>>(ei32, E, n);
    k_gemm1_hist<<<gemmBlocks + ge, B>>>(x, W1, ei32, E, n, gemmBlocks);
    k_scan1<<<nb, 1024>>>(n);
    k_scan2<<<1, 128>>>(n, nb);
    k_scan3<<<nb, 1024>>>(n);
    k_place<<<ge, B>>>(ei32, E, n);

    k_agg1 <<<ga, B>>>(b1, n);
    k_gemm2<<<(n + 127) / 128, 320>>>(W2, n);
    k_agg2 <<<ga, B>>>(b2, out, n);
}

// round 12
// speedup vs baseline: 1.4632x; 1.0073x over previous
#include <cuda_runtime.h>
#include <math.h>

#define NMAX 100000
#define EMAX 1600000
#define FIN  128
#define F1   64
#define F2   40
#define NB   ((NMAX + 1023) / 1024)   // 98 scan blocks

// ---------------- scratch (device globals) ---------------------------------
__device__ int    g_is64;                // 1 if edge_index is int64, 0 if int32
__device__ int    g_cnt [NMAX];
__device__ int    g_off [NMAX + 1];
__device__ int    g_pos [NMAX];
__device__ int    g_bsum[NB];
__device__ int    g_eidx[EMAX];          // src ids sorted by dst
__device__ float  g_dinv[NMAX];
__device__ float4 g_xw  [(size_t)NMAX * F1 / 4];  // RAW x@W1 (unscaled)
__device__ float4 g_h   [(size_t)NMAX * F1 / 4];  // relu output
__device__ float2 g_hws [(size_t)NMAX * F2 / 2];  // (h@W2)*dinv

// ---------------- fused: zero counters + dtype probe ------------------------
__global__ void k_zero_probe(const int* __restrict__ ei32, int E, int n) {
    if (blockIdx.x == 0) {
        int t = threadIdx.x;
        int nz = 0;
        int lim = (E < 1024) ? E : 1024;
        for (int i = t; i < lim; i += 256) nz |= ei32[2 * i + 1];
        int any = __syncthreads_or(nz);
        if (t == 0) g_is64 = (any == 0) ? 1 : 0;
    } else {
        int i = (blockIdx.x - 1) * 256 + threadIdx.x;
        if (i < n) { g_cnt[i] = 0; g_pos[i] = 0; }
    }
}

// ---------------- fused: GEMM1 (raw) + degree histogram ---------------------
__global__ void __launch_bounds__(256)
k_gemm1_hist(const float* __restrict__ x, const float* __restrict__ W,
             const int* __restrict__ ei32, int E, int n, int gemmBlocks) {
    __shared__ float ws[FIN * F1];  // 32 KB (idle for hist role)
    int tid = threadIdx.x;

    if (blockIdx.x >= gemmBlocks) {
        // ---- histogram role ----
        int e = (blockIdx.x - gemmBlocks) * 256 + tid;
        if (e >= E) return;
        int d;
        if (g_is64) d = (int)(((const long long*)ei32) + E)[e];
        else        d = ei32[E + e];
        if ((unsigned)d < (unsigned)n) atomicAdd(&g_cnt[d], 1);
        return;
    }

    // ---- GEMM1 role (raw output, no dinv) ----
    for (int i = tid; i < FIN * F1 / 4; i += 256)
        ((float4*)ws)[i] = ((const float4*)W)[i];
    __syncthreads();

    int sub = tid >> 3;            // 0..31
    int cg  = (tid & 7) * 8;       // column group start (32B aligned)
    int base = blockIdx.x * 128 + sub;

    float a[4][8];
#pragma unroll
    for (int r = 0; r < 4; r++)
#pragma unroll
        for (int j = 0; j < 8; j++) a[r][j] = 0.0f;

    const float4* xr[4];
#pragma unroll
    for (int r = 0; r < 4; r++) {
        int row = base + r * 32;
        int rc = (row < n) ? row : (n - 1);       // clamp; dup work, no trap
        xr[r] = (const float4*)(x + (size_t)rc * FIN);
    }

#pragma unroll 4
    for (int k4 = 0; k4 < FIN / 4; k4++) {
        float4 xv[4];
#pragma unroll
        for (int r = 0; r < 4; r++) xv[r] = xr[r][k4];
#pragma unroll
        for (int kk = 0; kk < 4; kk++) {
            const float4* wr = (const float4*)(ws + (k4 * 4 + kk) * F1 + cg);
            float4 wa = wr[0];
            float4 wb = wr[1];
#pragma unroll
            for (int r = 0; r < 4; r++) {
                float p = (kk == 0) ? xv[r].x : (kk == 1) ? xv[r].y
                        : (kk == 2) ? xv[r].z : xv[r].w;
                a[r][0] = fmaf(p, wa.x, a[r][0]);
                a[r][1] = fmaf(p, wa.y, a[r][1]);
                a[r][2] = fmaf(p, wa.z, a[r][2]);
                a[r][3] = fmaf(p, wa.w, a[r][3]);
                a[r][4] = fmaf(p, wb.x, a[r][4]);
                a[r][5] = fmaf(p, wb.y, a[r][5]);
                a[r][6] = fmaf(p, wb.z, a[r][6]);
                a[r][7] = fmaf(p, wb.w, a[r][7]);
            }
        }
    }

#pragma unroll
    for (int r = 0; r < 4; r++) {
        int row = base + r * 32;
        if (row >= n) break;
        float4* o = (float4*)((float*)g_xw + (size_t)row * F1 + cg);
        o[0] = make_float4(a[r][0], a[r][1], a[r][2], a[r][3]);
        o[1] = make_float4(a[r][4], a[r][5], a[r][6], a[r][7]);
    }
}

// ---------------- scans ------------------------------------------------------
__global__ void k_scan1(int n) {
    __shared__ int sh[2][1024];
    int tid = threadIdx.x;
    int i = blockIdx.x * 1024 + tid;
    int x = (i < n) ? g_cnt[i] : 0;
    sh[0][tid] = x;
    int pin = 0;
    for (int off = 1; off < 1024; off <<= 1) {
        __syncthreads();
        int v = sh[pin][tid];
        if (tid >= off) v += sh[pin][tid - off];
        sh[1 - pin][tid] = v;
        pin = 1 - pin;
    }
    __syncthreads();
    int inc = sh[pin][tid];
    if (i < n) g_off[i] = inc - x;             // exclusive, pre-block-offset
    if (tid == 1023) g_bsum[blockIdx.x] = inc; // block total
}

// each block sums its bsum prefix (98 independent loads), adds offsets, dinv
__global__ void k_scan3(int n, int nb) {
    __shared__ int boff_sh;
    if (threadIdx.x == 0) {
        int run = 0;
        for (int b = 0; b < blockIdx.x; b++) run += g_bsum[b];
        boff_sh = run;
        if (blockIdx.x == nb - 1) g_off[n] = run + g_bsum[nb - 1];
    }
    __syncthreads();
    int i = blockIdx.x * 1024 + threadIdx.x;
    if (i < n) {
        g_off[i] += boff_sh;
        g_dinv[i] = rsqrtf((float)(g_cnt[i] + 1));   // +1 self-loop
    }
}

__global__ void k_place(const int* __restrict__ ei32, int E, int n) {
    int e = blockIdx.x * blockDim.x + threadIdx.x;
    if (e >= E) return;
    int d, s;
    if (g_is64) {
        const long long* e64 = (const long long*)ei32;
        d = (int)e64[E + e];
        s = (int)e64[e];
    } else {
        d = ei32[E + e];
        s = ei32[e];
    }
    if ((unsigned)d >= (unsigned)n) return;
    if ((unsigned)s >= (unsigned)n) s = 0;
    int slot = g_off[d] + atomicAdd(&g_pos[d], 1);
    if (slot < EMAX) g_eidx[slot] = s;
}

// ---------------- aggregation layer1: warp/node, 2 edges/row-load ----------
// 16 lanes x float4 cover one 256B row; halves process even/odd edges.
__global__ void k_agg1(const float* __restrict__ b1, int n) {
    int lane = threadIdx.x & 31;
    int w = blockIdx.x * 8 + (threadIdx.x >> 5);
    if (w >= n) return;

    int half = lane >> 4;          // 0: even edges, 1: odd edges
    int q    = lane & 15;          // float4 index within 64-float row
    int beg = g_off[w], end = g_off[w + 1];

    float4 acc = make_float4(0.f, 0.f, 0.f, 0.f);
    int k = beg + half;
    for (; k + 6 < end; k += 8) {            // 4 pairs -> 8 edges in flight
        int s0 = g_eidx[k];
        int s1 = g_eidx[k + 2];
        int s2 = g_eidx[k + 4];
        int s3 = g_eidx[k + 6];
        float d0 = g_dinv[s0], d1 = g_dinv[s1];
        float d2 = g_dinv[s2], d3 = g_dinv[s3];
        float4 u0 = g_xw[(size_t)s0 * 16 + q];
        float4 u1 = g_xw[(size_t)s1 * 16 + q];
        float4 u2 = g_xw[(size_t)s2 * 16 + q];
        float4 u3 = g_xw[(size_t)s3 * 16 + q];
        acc.x = fmaf(d0, u0.x, acc.x); acc.y = fmaf(d0, u0.y, acc.y);
        acc.z = fmaf(d0, u0.z, acc.z); acc.w = fmaf(d0, u0.w, acc.w);
        acc.x = fmaf(d1, u1.x, acc.x); acc.y = fmaf(d1, u1.y, acc.y);
        acc.z = fmaf(d1, u1.z, acc.z); acc.w = fmaf(d1, u1.w, acc.w);
        acc.x = fmaf(d2, u2.x, acc.x); acc.y = fmaf(d2, u2.y, acc.y);
        acc.z = fmaf(d2, u2.z, acc.z); acc.w = fmaf(d2, u2.w, acc.w);
        acc.x = fmaf(d3, u3.x, acc.x); acc.y = fmaf(d3, u3.y, acc.y);
        acc.z = fmaf(d3, u3.z, acc.z); acc.w = fmaf(d3, u3.w, acc.w);
    }
    for (; k < end; k += 2) {
        int s = g_eidx[k];
        float ds = g_dinv[s];
        float4 u = g_xw[(size_t)s * 16 + q];
        acc.x = fmaf(ds, u.x, acc.x); acc.y = fmaf(ds, u.y, acc.y);
        acc.z = fmaf(ds, u.z, acc.z); acc.w = fmaf(ds, u.w, acc.w);
    }

    // combine even/odd halves (lane q gets lane q+16's partial)
    acc.x += __shfl_xor_sync(0xFFFFFFFFu, acc.x, 16);
    acc.y += __shfl_xor_sync(0xFFFFFFFFu, acc.y, 16);
    acc.z += __shfl_xor_sync(0xFFFFFFFFu, acc.z, 16);
    acc.w += __shfl_xor_sync(0xFFFFFFFFu, acc.w, 16);

    if (half == 0) {
        float sc = g_dinv[w];
        float4 sv = g_xw[(size_t)w * 16 + q];    // self-loop (dinv[w]*xw[w])
        acc.x = fmaf(sv.x, sc, acc.x);
        acc.y = fmaf(sv.y, sc, acc.y);
        acc.z = fmaf(sv.z, sc, acc.z);
        acc.w = fmaf(sv.w, sc, acc.w);
        float4 bb = ((const float4*)b1)[q];
        float4 r;
        r.x = fmaxf(fmaf(acc.x, sc, bb.x), 0.0f);
        r.y = fmaxf(fmaf(acc.y, sc, bb.y), 0.0f);
        r.z = fmaxf(fmaf(acc.z, sc, bb.z), 0.0f);
        r.w = fmaxf(fmaf(acc.w, sc, bb.w), 0.0f);
        g_h[(size_t)w * 16 + q] = r;
    }
}

// ---------------- GEMM2: hws = (h @ W2) * dinv[row] ------------------------
__global__ void k_gemm2(const float* __restrict__ W, int n) {
    __shared__ float ws[F1 * F2];  // 10.24 KB
    int tid = threadIdx.x;
    for (int i = tid; i < F1 * F2; i += 320) ws[i] = W[i];
    __syncthreads();

    int sub = tid / 5;              // 0..63
    int cg  = (tid % 5) * 8;        // column group start (32B aligned)
    int r0 = blockIdx.x * 128 + sub;
    int r1 = r0 + 64;
    if (r0 >= n) return;
    bool v1 = (r1 < n);

    float a00 = 0.f, a01 = 0.f, a02 = 0.f, a03 = 0.f;
    float a04 = 0.f, a05 = 0.f, a06 = 0.f, a07 = 0.f;
    float a10 = 0.f, a11 = 0.f, a12 = 0.f, a13 = 0.f;
    float a14 = 0.f, a15 = 0.f, a16 = 0.f, a17 = 0.f;

    const float4* hr0 = (const float4*)((const float*)g_h + (size_t)r0 * F1);
    const float4* hr1 = (const float4*)((const float*)g_h + (size_t)(v1 ? r1 : r0) * F1);
#pragma unroll 4
    for (int k4 = 0; k4 < F1 / 4; k4++) {
        float4 ha = hr0[k4];
        float4 hb = hr1[k4];
        float h0[4] = {ha.x, ha.y, ha.z, ha.w};
        float h1[4] = {hb.x, hb.y, hb.z, hb.w};
#pragma unroll
        for (int kk = 0; kk < 4; kk++) {
            const float4* wr = (const float4*)(ws + (k4 * 4 + kk) * F2 + cg);
            float4 wa = wr[0];
            float4 wb = wr[1];
            float p0 = h0[kk], p1 = h1[kk];
            a00 = fmaf(p0, wa.x, a00); a10 = fmaf(p1, wa.x, a10);
            a01 = fmaf(p0, wa.y, a01); a11 = fmaf(p1, wa.y, a11);
            a02 = fmaf(p0, wa.z, a02); a12 = fmaf(p1, wa.z, a12);
            a03 = fmaf(p0, wa.w, a03); a13 = fmaf(p1, wa.w, a13);
            a04 = fmaf(p0, wb.x, a04); a14 = fmaf(p1, wb.x, a14);
            a05 = fmaf(p0, wb.y, a05); a15 = fmaf(p1, wb.y, a15);
            a06 = fmaf(p0, wb.z, a06); a16 = fmaf(p1, wb.z, a16);
            a07 = fmaf(p0, wb.w, a07); a17 = fmaf(p1, wb.w, a17);
        }
    }

    float s0 = g_dinv[r0];
    float4* o0 = (float4*)((float*)g_hws + (size_t)r0 * F2 + cg);
    o0[0] = make_float4(a00 * s0, a01 * s0, a02 * s0, a03 * s0);
    o0[1] = make_float4(a04 * s0, a05 * s0, a06 * s0, a07 * s0);
    if (v1) {
        float s1 = g_dinv[r1];
        float4* o1 = (float4*)((float*)g_hws + (size_t)r1 * F2 + cg);
        o1[0] = make_float4(a10 * s1, a11 * s1, a12 * s1, a13 * s1);
        o1[1] = make_float4(a14 * s1, a15 * s1, a16 * s1, a17 * s1);
    }
}

// ---------------- aggregation layer2 + bias + log_softmax (8-edge MLP) -----
__global__ void k_agg2(const float* __restrict__ b2, float* __restrict__ out, int n) {
    int lane = threadIdx.x & 31;
    int w = blockIdx.x * 8 + (threadIdx.x >> 5);
    if (w >= n) return;

    bool act = (lane < F2 / 2);
    int li = act ? lane : 0;
    int beg = g_off[w], end = g_off[w + 1];
    size_t self = (size_t)w * (F2 / 2) + li;

    float2 acc = g_hws[self];
    int k = beg;
    for (; k + 7 < end; k += 8) {
        int s0 = g_eidx[k],     s1 = g_eidx[k + 1];
        int s2 = g_eidx[k + 2], s3 = g_eidx[k + 3];
        int s4 = g_eidx[k + 4], s5 = g_eidx[k + 5];
        int s6 = g_eidx[k + 6], s7 = g_eidx[k + 7];
        float2 u0 = g_hws[(size_t)s0 * (F2 / 2) + li];
        float2 u1 = g_hws[(size_t)s1 * (F2 / 2) + li];
        float2 u2 = g_hws[(size_t)s2 * (F2 / 2) + li];
        float2 u3 = g_hws[(size_t)s3 * (F2 / 2) + li];
        float2 u4 = g_hws[(size_t)s4 * (F2 / 2) + li];
        float2 u5 = g_hws[(size_t)s5 * (F2 / 2) + li];
        float2 u6 = g_hws[(size_t)s6 * (F2 / 2) + li];
        float2 u7 = g_hws[(size_t)s7 * (F2 / 2) + li];
        acc.x += ((u0.x + u1.x) + (u2.x + u3.x)) + ((u4.x + u5.x) + (u6.x + u7.x));
        acc.y += ((u0.y + u1.y) + (u2.y + u3.y)) + ((u4.y + u5.y) + (u6.y + u7.y));
    }
    for (; k < end; k++) {
        float2 u = g_hws[(size_t)g_eidx[k] * (F2 / 2) + li];
        acc.x += u.x;
        acc.y += u.y;
    }

    float sc = g_dinv[w];
    float zx = fmaf(acc.x, sc, b2[2 * li]);
    float zy = fmaf(acc.y, sc, b2[2 * li + 1]);

    float m = act ? fmaxf(zx, zy) : -1e30f;
#pragma unroll
    for (int o = 16; o > 0; o >>= 1)
        m = fmaxf(m, __shfl_xor_sync(0xFFFFFFFFu, m, o));

    float sum = act ? (expf(zx - m) + expf(zy - m)) : 0.0f;
#pragma unroll
    for (int o = 16; o > 0; o >>= 1)
        sum += __shfl_xor_sync(0xFFFFFFFFu, sum, o);

    float lse = m + logf(sum);
    if (act) {
        float2* o2 = (float2*)(out + (size_t)w * F2 + 2 * li);
        *o2 = make_float2(zx - lse, zy - lse);
    }
}

// ---------------- launcher --------------------------------------------------
extern "C" void kernel_launch(void* const* d_in, const int* in_sizes, int n_in,
                              void* d_out, int out_size) {
    const float* x    = (const float*)d_in[0];
    const int*   ei32 = (const int*)d_in[1];   // int32 words (probed for int64)
    const float* W1   = (const float*)d_in[2];
    const float* b1   = (const float*)d_in[3];
    const float* W2   = (const float*)d_in[4];
    const float* b2   = (const float*)d_in[5];
    float*       out  = (float*)d_out;

    int n = in_sizes[0] / FIN;       // 100000
    int E = in_sizes[1] / 2;         // 1600000

    const int B = 256;
    int gn = (n + B - 1) / B;
    int ge = (E + B - 1) / B;
    int nb = (n + 1023) / 1024;      // 98
    int ga = (n + 7) / 8;            // warp-per-node grids
    int gemmBlocks = (n + 127) / 128;

    k_zero_probe<<<gn + 1, B>>>(ei32, E, n);
    k_gemm1_hist<<<gemmBlocks + ge, B>>>(x, W1, ei32, E, n, gemmBlocks);
    k_scan1<<<nb, 1024>>>(n);
    k_scan3<<<nb, 1024>>>(n, nb);
    k_place<<<ge, B>>>(ei32, E, n);

    k_agg1 <<<ga, B>>>(b1, n);
    k_gemm2<<<(n + 127) / 128, 320>>>(W2, n);
    k_agg2 <<<ga, B>>>(b2, out, n);
}

// round 13
// speedup vs baseline: 1.4879x; 1.0169x over previous
#include <cuda_runtime.h>
#include <cuda_fp16.h>
#include <math.h>

#define NMAX 100000
#define EMAX 1600000
#define FIN  128
#define F1   64
#define F2   40
#define NB   ((NMAX + 1023) / 1024)   // 98 scan blocks

// ---------------- scratch (device globals) ---------------------------------
__device__ int    g_is64;                // 1 if edge_index is int64, 0 if int32
__device__ int    g_cnt [NMAX];
__device__ int    g_off [NMAX + 1];
__device__ int    g_pos [NMAX];
__device__ int    g_bsum[NB];
__device__ int    g_eidx[EMAX];          // src ids sorted by dst
__device__ float  g_dinv[NMAX];
__device__ uint4  g_xwh [(size_t)NMAX * 8];   // RAW x@W1, fp16x2 words (32 uints/row)
__device__ float4 g_h   [(size_t)NMAX * F1 / 4];  // relu output (fp32)
__device__ uint4  g_hwsh[(size_t)NMAX * 5];   // (h@W2)*dinv, fp16 (20 uints/row)

// ---------------- fused: zero counters + dtype probe ------------------------
__global__ void k_zero_probe(const int* __restrict__ ei32, int E, int n) {
    if (blockIdx.x == 0) {
        int t = threadIdx.x;
        int nz = 0;
        int lim = (E < 1024) ? E : 1024;
        for (int i = t; i < lim; i += 256) nz |= ei32[2 * i + 1];
        int any = __syncthreads_or(nz);
        if (t == 0) g_is64 = (any == 0) ? 1 : 0;
    } else {
        int i = (blockIdx.x - 1) * 256 + threadIdx.x;
        if (i < n) { g_cnt[i] = 0; g_pos[i] = 0; }
    }
}

// ---------------- fused: GEMM1 (raw, fp16 out) + degree histogram -----------
__global__ void __launch_bounds__(256)
k_gemm1_hist(const float* __restrict__ x, const float* __restrict__ W,
             const int* __restrict__ ei32, int E, int n, int gemmBlocks) {
    __shared__ float ws[FIN * F1];  // 32 KB (idle for hist role)
    int tid = threadIdx.x;

    if (blockIdx.x >= gemmBlocks) {
        // ---- histogram role ----
        int e = (blockIdx.x - gemmBlocks) * 256 + tid;
        if (e >= E) return;
        int d;
        if (g_is64) d = (int)(((const long long*)ei32) + E)[e];
        else        d = ei32[E + e];
        if ((unsigned)d < (unsigned)n) atomicAdd(&g_cnt[d], 1);
        return;
    }

    // ---- GEMM1 role ----
    for (int i = tid; i < FIN * F1 / 4; i += 256)
        ((float4*)ws)[i] = ((const float4*)W)[i];
    __syncthreads();

    int sub = tid >> 3;            // 0..31
    int cg  = (tid & 7) * 8;       // column group start
    int base = blockIdx.x * 128 + sub;

    float a[4][8];
#pragma unroll
    for (int r = 0; r < 4; r++)
#pragma unroll
        for (int j = 0; j < 8; j++) a[r][j] = 0.0f;

    const float4* xr[4];
#pragma unroll
    for (int r = 0; r < 4; r++) {
        int row = base + r * 32;
        int rc = (row < n) ? row : (n - 1);       // clamp; dup work, no trap
        xr[r] = (const float4*)(x + (size_t)rc * FIN);
    }

#pragma unroll 4
    for (int k4 = 0; k4 < FIN / 4; k4++) {
        float4 xv[4];
#pragma unroll
        for (int r = 0; r < 4; r++) xv[r] = xr[r][k4];
#pragma unroll
        for (int kk = 0; kk < 4; kk++) {
            const float4* wr = (const float4*)(ws + (k4 * 4 + kk) * F1 + cg);
            float4 wa = wr[0];
            float4 wb = wr[1];
#pragma unroll
            for (int r = 0; r < 4; r++) {
                float p = (kk == 0) ? xv[r].x : (kk == 1) ? xv[r].y
                        : (kk == 2) ? xv[r].z : xv[r].w;
                a[r][0] = fmaf(p, wa.x, a[r][0]);
                a[r][1] = fmaf(p, wa.y, a[r][1]);
                a[r][2] = fmaf(p, wa.z, a[r][2]);
                a[r][3] = fmaf(p, wa.w, a[r][3]);
                a[r][4] = fmaf(p, wb.x, a[r][4]);
                a[r][5] = fmaf(p, wb.y, a[r][5]);
                a[r][6] = fmaf(p, wb.z, a[r][6]);
                a[r][7] = fmaf(p, wb.w, a[r][7]);
            }
        }
    }

#pragma unroll
    for (int r = 0; r < 4; r++) {
        int row = base + r * 32;
        if (row >= n) break;
        __half2 h0 = __float22half2_rn(make_float2(a[r][0], a[r][1]));
        __half2 h1 = __float22half2_rn(make_float2(a[r][2], a[r][3]));
        __half2 h2 = __float22half2_rn(make_float2(a[r][4], a[r][5]));
        __half2 h3 = __float22half2_rn(make_float2(a[r][6], a[r][7]));
        uint4 pk;
        pk.x = *(unsigned*)&h0; pk.y = *(unsigned*)&h1;
        pk.z = *(unsigned*)&h2; pk.w = *(unsigned*)&h3;
        // row has 32 uints = 8 uint4; this thread owns uint4 index cg/8... cg is
        // float col start (mult of 8) -> uint4 index cg/8 within row
        ((uint4*)g_xwh)[(size_t)row * 8 + (cg >> 3)] = pk;
    }
}

// ---------------- scans ------------------------------------------------------
__global__ void k_scan1(int n) {
    __shared__ int sh[2][1024];
    int tid = threadIdx.x;
    int i = blockIdx.x * 1024 + tid;
    int x = (i < n) ? g_cnt[i] : 0;
    sh[0][tid] = x;
    int pin = 0;
    for (int off = 1; off < 1024; off <<= 1) {
        __syncthreads();
        int v = sh[pin][tid];
        if (tid >= off) v += sh[pin][tid - off];
        sh[1 - pin][tid] = v;
        pin = 1 - pin;
    }
    __syncthreads();
    int inc = sh[pin][tid];
    if (i < n) g_off[i] = inc - x;             // exclusive, pre-block-offset
    if (tid == 1023) g_bsum[blockIdx.x] = inc; // block total
}

__global__ void k_scan3(int n, int nb) {
    __shared__ int boff_sh;
    if (threadIdx.x == 0) {
        int run = 0;
        for (int b = 0; b < blockIdx.x; b++) run += g_bsum[b];
        boff_sh = run;
        if (blockIdx.x == nb - 1) g_off[n] = run + g_bsum[nb - 1];
    }
    __syncthreads();
    int i = blockIdx.x * 1024 + threadIdx.x;
    if (i < n) {
        g_off[i] += boff_sh;
        g_dinv[i] = rsqrtf((float)(g_cnt[i] + 1));   // +1 self-loop
    }
}

__global__ void k_place(const int* __restrict__ ei32, int E, int n) {
    int e = blockIdx.x * blockDim.x + threadIdx.x;
    if (e >= E) return;
    int d, s;
    if (g_is64) {
        const long long* e64 = (const long long*)ei32;
        d = (int)e64[E + e];
        s = (int)e64[e];
    } else {
        d = ei32[E + e];
        s = ei32[e];
    }
    if ((unsigned)d >= (unsigned)n) return;
    if ((unsigned)s >= (unsigned)n) s = 0;
    int slot = g_off[d] + atomicAdd(&g_pos[d], 1);
    if (slot < EMAX) g_eidx[slot] = s;
}

// ---------------- aggregation layer1 (warp/node, fp16 gather, 8-edge MLP) ---
// Lane l owns features 2l, 2l+1 as one half2 word; a row = one 128B line.
__global__ void k_agg1(const float* __restrict__ b1, int n) {
    int lane = threadIdx.x & 31;
    int w = blockIdx.x * 8 + (threadIdx.x >> 5);
    if (w >= n) return;

    const unsigned* xw = (const unsigned*)g_xwh;   // 32 uints per row
    int beg = g_off[w], end = g_off[w + 1];

    float accx = 0.f, accy = 0.f;
    int k = beg;
    for (; k + 7 < end; k += 8) {
        int s0 = g_eidx[k],     s1 = g_eidx[k + 1];
        int s2 = g_eidx[k + 2], s3 = g_eidx[k + 3];
        int s4 = g_eidx[k + 4], s5 = g_eidx[k + 5];
        int s6 = g_eidx[k + 6], s7 = g_eidx[k + 7];
        float d0 = g_dinv[s0], d1 = g_dinv[s1], d2 = g_dinv[s2], d3 = g_dinv[s3];
        float d4 = g_dinv[s4], d5 = g_dinv[s5], d6 = g_dinv[s6], d7 = g_dinv[s7];
        unsigned u0 = xw[(size_t)s0 * 32 + lane];
        unsigned u1 = xw[(size_t)s1 * 32 + lane];
        unsigned u2 = xw[(size_t)s2 * 32 + lane];
        unsigned u3 = xw[(size_t)s3 * 32 + lane];
        unsigned u4 = xw[(size_t)s4 * 32 + lane];
        unsigned u5 = xw[(size_t)s5 * 32 + lane];
        unsigned u6 = xw[(size_t)s6 * 32 + lane];
        unsigned u7 = xw[(size_t)s7 * 32 + lane];
        float2 f0 = __half22float2(*(__half2*)&u0);
        float2 f1 = __half22float2(*(__half2*)&u1);
        float2 f2 = __half22float2(*(__half2*)&u2);
        float2 f3 = __half22float2(*(__half2*)&u3);
        float2 f4 = __half22float2(*(__half2*)&u4);
        float2 f5 = __half22float2(*(__half2*)&u5);
        float2 f6 = __half22float2(*(__half2*)&u6);
        float2 f7 = __half22float2(*(__half2*)&u7);
        accx = fmaf(d0, f0.x, accx); accy = fmaf(d0, f0.y, accy);
        accx = fmaf(d1, f1.x, accx); accy = fmaf(d1, f1.y, accy);
        accx = fmaf(d2, f2.x, accx); accy = fmaf(d2, f2.y, accy);
        accx = fmaf(d3, f3.x, accx); accy = fmaf(d3, f3.y, accy);
        accx = fmaf(d4, f4.x, accx); accy = fmaf(d4, f4.y, accy);
        accx = fmaf(d5, f5.x, accx); accy = fmaf(d5, f5.y, accy);
        accx = fmaf(d6, f6.x, accx); accy = fmaf(d6, f6.y, accy);
        accx = fmaf(d7, f7.x, accx); accy = fmaf(d7, f7.y, accy);
    }
    for (; k < end; k++) {
        int s = g_eidx[k];
        float ds = g_dinv[s];
        unsigned u = xw[(size_t)s * 32 + lane];
        float2 f = __half22float2(*(__half2*)&u);
        accx = fmaf(ds, f.x, accx);
        accy = fmaf(ds, f.y, accy);
    }

    float sc = g_dinv[w];
    unsigned su = xw[(size_t)w * 32 + lane];        // self-loop
    float2 sf = __half22float2(*(__half2*)&su);
    accx = fmaf(sc, sf.x, accx);
    accy = fmaf(sc, sf.y, accy);

    float bx = b1[2 * lane], by = b1[2 * lane + 1];
    float2 r;
    r.x = fmaxf(fmaf(accx, sc, bx), 0.0f);
    r.y = fmaxf(fmaf(accy, sc, by), 0.0f);
    ((float2*)g_h)[(size_t)w * 32 + lane] = r;
}

// ---------------- GEMM2: hws = (h @ W2) * dinv[row], fp16 out ---------------
__global__ void k_gemm2(const float* __restrict__ W, int n) {
    __shared__ float ws[F1 * F2];  // 10.24 KB
    int tid = threadIdx.x;
    for (int i = tid; i < F1 * F2; i += 320) ws[i] = W[i];
    __syncthreads();

    int sub = tid / 5;              // 0..63
    int cg  = (tid % 5) * 8;        // column group start
    int r0 = blockIdx.x * 128 + sub;
    int r1 = r0 + 64;
    if (r0 >= n) return;
    bool v1 = (r1 < n);

    float a00 = 0.f, a01 = 0.f, a02 = 0.f, a03 = 0.f;
    float a04 = 0.f, a05 = 0.f, a06 = 0.f, a07 = 0.f;
    float a10 = 0.f, a11 = 0.f, a12 = 0.f, a13 = 0.f;
    float a14 = 0.f, a15 = 0.f, a16 = 0.f, a17 = 0.f;

    const float4* hr0 = (const float4*)((const float*)g_h + (size_t)r0 * F1);
    const float4* hr1 = (const float4*)((const float*)g_h + (size_t)(v1 ? r1 : r0) * F1);
#pragma unroll 4
    for (int k4 = 0; k4 < F1 / 4; k4++) {
        float4 ha = hr0[k4];
        float4 hb = hr1[k4];
        float h0[4] = {ha.x, ha.y, ha.z, ha.w};
        float h1[4] = {hb.x, hb.y, hb.z, hb.w};
#pragma unroll
        for (int kk = 0; kk < 4; kk++) {
            const float4* wr = (const float4*)(ws + (k4 * 4 + kk) * F2 + cg);
            float4 wa = wr[0];
            float4 wb = wr[1];
            float p0 = h0[kk], p1 = h1[kk];
            a00 = fmaf(p0, wa.x, a00); a10 = fmaf(p1, wa.x, a10);
            a01 = fmaf(p0, wa.y, a01); a11 = fmaf(p1, wa.y, a11);
            a02 = fmaf(p0, wa.z, a02); a12 = fmaf(p1, wa.z, a12);
            a03 = fmaf(p0, wa.w, a03); a13 = fmaf(p1, wa.w, a13);
            a04 = fmaf(p0, wb.x, a04); a14 = fmaf(p1, wb.x, a14);
            a05 = fmaf(p0, wb.y, a05); a15 = fmaf(p1, wb.y, a15);
            a06 = fmaf(p0, wb.z, a06); a16 = fmaf(p1, wb.z, a16);
            a07 = fmaf(p0, wb.w, a07); a17 = fmaf(p1, wb.w, a17);
        }
    }

    float s0 = g_dinv[r0];
    {
        __half2 h0 = __float22half2_rn(make_float2(a00 * s0, a01 * s0));
        __half2 h1 = __float22half2_rn(make_float2(a02 * s0, a03 * s0));
        __half2 h2 = __float22half2_rn(make_float2(a04 * s0, a05 * s0));
        __half2 h3 = __float22half2_rn(make_float2(a06 * s0, a07 * s0));
        uint4 pk;
        pk.x = *(unsigned*)&h0; pk.y = *(unsigned*)&h1;
        pk.z = *(unsigned*)&h2; pk.w = *(unsigned*)&h3;
        ((uint4*)g_hwsh)[(size_t)r0 * 5 + (cg >> 3)] = pk;
    }
    if (v1) {
        float s1 = g_dinv[r1];
        __half2 h0 = __float22half2_rn(make_float2(a10 * s1, a11 * s1));
        __half2 h1 = __float22half2_rn(make_float2(a12 * s1, a13 * s1));
        __half2 h2 = __float22half2_rn(make_float2(a14 * s1, a15 * s1));
        __half2 h3 = __float22half2_rn(make_float2(a16 * s1, a17 * s1));
        uint4 pk;
        pk.x = *(unsigned*)&h0; pk.y = *(unsigned*)&h1;
        pk.z = *(unsigned*)&h2; pk.w = *(unsigned*)&h3;
        ((uint4*)g_hwsh)[(size_t)r1 * 5 + (cg >> 3)] = pk;
    }
}

// ---------------- aggregation layer2 + bias + log_softmax (fp16 gather) ----
__global__ void k_agg2(const float* __restrict__ b2, float* __restrict__ out, int n) {
    int lane = threadIdx.x & 31;
    int w = blockIdx.x * 8 + (threadIdx.x >> 5);
    if (w >= n) return;

    bool act = (lane < F2 / 2);
    int li = act ? lane : 0;
    const unsigned* hw = (const unsigned*)g_hwsh;   // 20 uints per row
    int beg = g_off[w], end = g_off[w + 1];

    float accx = 0.f, accy = 0.f;
    int k = beg;
    for (; k + 7 < end; k += 8) {
        int s0 = g_eidx[k],     s1 = g_eidx[k + 1];
        int s2 = g_eidx[k + 2], s3 = g_eidx[k + 3];
        int s4 = g_eidx[k + 4], s5 = g_eidx[k + 5];
        int s6 = g_eidx[k + 6], s7 = g_eidx[k + 7];
        unsigned u0 = hw[(size_t)s0 * 20 + li];
        unsigned u1 = hw[(size_t)s1 * 20 + li];
        unsigned u2 = hw[(size_t)s2 * 20 + li];
        unsigned u3 = hw[(size_t)s3 * 20 + li];
        unsigned u4 = hw[(size_t)s4 * 20 + li];
        unsigned u5 = hw[(size_t)s5 * 20 + li];
        unsigned u6 = hw[(size_t)s6 * 20 + li];
        unsigned u7 = hw[(size_t)s7 * 20 + li];
        float2 f0 = __half22float2(*(__half2*)&u0);
        float2 f1 = __half22float2(*(__half2*)&u1);
        float2 f2 = __half22float2(*(__half2*)&u2);
        float2 f3 = __half22float2(*(__half2*)&u3);
        float2 f4 = __half22float2(*(__half2*)&u4);
        float2 f5 = __half22float2(*(__half2*)&u5);
        float2 f6 = __half22float2(*(__half2*)&u6);
        float2 f7 = __half22float2(*(__half2*)&u7);
        accx += ((f0.x + f1.x) + (f2.x + f3.x)) + ((f4.x + f5.x) + (f6.x + f7.x));
        accy += ((f0.y + f1.y) + (f2.y + f3.y)) + ((f4.y + f5.y) + (f6.y + f7.y));
    }
    for (; k < end; k++) {
        unsigned u = hw[(size_t)g_eidx[k] * 20 + li];
        float2 f = __half22float2(*(__half2*)&u);
        accx += f.x;
        accy += f.y;
    }

    {   // self-loop
        unsigned su = hw[(size_t)w * 20 + li];
        float2 sf = __half22float2(*(__half2*)&su);
        accx += sf.x;
        accy += sf.y;
    }

    float sc = g_dinv[w];
    float zx = fmaf(accx, sc, b2[2 * li]);
    float zy = fmaf(accy, sc, b2[2 * li + 1]);

    float m = act ? fmaxf(zx, zy) : -1e30f;
#pragma unroll
    for (int o = 16; o > 0; o >>= 1)
        m = fmaxf(m, __shfl_xor_sync(0xFFFFFFFFu, m, o));

    float sum = act ? (expf(zx - m) + expf(zy - m)) : 0.0f;
#pragma unroll
    for (int o = 16; o > 0; o >>= 1)
        sum += __shfl_xor_sync(0xFFFFFFFFu, sum, o);

    float lse = m + logf(sum);
    if (act) {
        float2* o2 = (float2*)(out + (size_t)w * F2 + 2 * li);
        *o2 = make_float2(zx - lse, zy - lse);
    }
}

// ---------------- launcher --------------------------------------------------
extern "C" void kernel_launch(void* const* d_in, const int* in_sizes, int n_in,
                              void* d_out, int out_size) {
    const float* x    = (const float*)d_in[0];
    const int*   ei32 = (const int*)d_in[1];   // int32 words (probed for int64)
    const float* W1   = (const float*)d_in[2];
    const float* b1   = (const float*)d_in[3];
    const float* W2   = (const float*)d_in[4];
    const float* b2   = (const float*)d_in[5];
    float*       out  = (float*)d_out;

    int n = in_sizes[0] / FIN;       // 100000
    int E = in_sizes[1] / 2;         // 1600000

    const int B = 256;
    int gn = (n + B - 1) / B;
    int ge = (E + B - 1) / B;
    int nb = (n + 1023) / 1024;      // 98
    int ga = (n + 7) / 8;            // warp-per-node grids
    int gemmBlocks = (n + 127) / 128;

    k_zero_probe<<<gn + 1, B>>>(ei32, E, n);
    k_gemm1_hist<<<gemmBlocks + ge, B>>>(x, W1, ei32, E, n, gemmBlocks);
    k_scan1<<<nb, 1024>>>(n);
    k_scan3<<<nb, 1024>>>(n, nb);
    k_place<<<ge, B>>>(ei32, E, n);

    k_agg1 <<<ga, B>>>(b1, n);
    k_gemm2<<<(n + 127) / 128, 320>>>(W2, n);
    k_agg2 <<<ga, B>>>(b2, out, n);
}